// round 5
// baseline (speedup 1.0000x reference)
#include <cuda_runtime.h>
#include <cuda_bf16.h>
#include <cstdint>
#include <math.h>

#define BB   4
#define CIN  64
#define HID  64
#define HH   64
#define WW   64
#define NN   9
#define DD   256
#define INCC 128
#define OUTC 256
#define HP   66
#define HW   4096
#define KTOT 1152         // INCC * NN
#define KROW (KTOT * 2)   // bf16 hi|lo packed row length (elements)

// ---- scratch (static device globals; no allocation allowed) ----
__device__ float g_xpad[BB * INCC * HP * HP];
__device__ float g_wm1t[BB * DD * INCC];
__device__ __nv_bfloat16 g_wm2[(size_t)BB * OUTC * KROW];    // A hi|lo, gate-interleaved rows
__device__ float g_bm[BB * OUTC];                             // original order
__device__ float g_off[BB * 18 * HW];
__device__ __nv_bfloat16 g_xoffT2[(size_t)BB * HW * KROW];   // B hi|lo packed

// ============================================================
__device__ __forceinline__ uint32_t smem_u32(const void* p) {
    uint32_t a;
    asm("{ .reg .u64 t; cvta.to.shared.u64 t, %1; cvt.u32.u64 %0, t; }" : "=r"(a) : "l"(p));
    return a;
}
#define CP_ASYNC16(dst, src) \
    asm volatile("cp.async.cg.shared.global [%0], [%1], 16;" :: "r"(dst), "l"(src))
#define CP_COMMIT() asm volatile("cp.async.commit_group;" ::: "memory")

#define LDMX4(r, addr) \
    asm volatile("ldmatrix.sync.aligned.m8n8.x4.shared.b16 {%0,%1,%2,%3}, [%4];" \
        : "=r"((r)[0]), "=r"((r)[1]), "=r"((r)[2]), "=r"((r)[3]) : "r"(addr))

__device__ __forceinline__ void mma_bf16(float* c, const uint32_t* a, const uint32_t* b) {
    asm volatile(
        "mma.sync.aligned.m16n8k16.row.col.f32.bf16.bf16.f32 "
        "{%0,%1,%2,%3}, {%4,%5,%6,%7}, {%8,%9}, {%0,%1,%2,%3};"
        : "+f"(c[0]), "+f"(c[1]), "+f"(c[2]), "+f"(c[3])
        : "r"(a[0]), "r"(a[1]), "r"(a[2]), "r"(a[3]), "r"(b[0]), "r"(b[1]));
}

__device__ __forceinline__ void store_hilo(__nv_bfloat16* rowbase, int k, float v) {
    __nv_bfloat16 hi = __float2bfloat16(v);
    float lo = v - __bfloat162float(hi);
    size_t base = (size_t)(k >> 5) * 64 + (k & 31);
    rowbase[base]      = hi;
    rowbase[base + 32] = __float2bfloat16(lo);
}

// ---------------------------------------------------------------
// 0) zero-padded concat(input, h_cur): (b, 128, 66, 66)
__global__ void k_xpad(const float* __restrict__ inp, const float* __restrict__ hcur) {
    int idx = blockIdx.x * 256 + threadIdx.x;
    if (idx >= BB * INCC * HP * HP) return;
    int xy = idx % (HP * HP);
    int bc = idx / (HP * HP);
    int y = xy / HP, x = xy % HP;
    int c = bc % INCC, b = bc / INCC;
    float v = 0.f;
    if (y >= 1 && y <= HH && x >= 1 && x <= WW) {
        int pix = (y - 1) * WW + (x - 1);
        if (c < CIN) v = inp[((size_t)(b * CIN + c)) * HW + pix];
        else         v = hcur[((size_t)(b * HID + (c - CIN))) * HW + pix];
    }
    g_xpad[idx] = v;
}

// ---------------------------------------------------------------
// 1) wm1t[b][d][c] = meta[b] . w1_w[c*D+d] + w1_b[c*D+d]   (warp-per-output)
__global__ void k_wm1(const float* __restrict__ meta, const float* __restrict__ w1w,
                      const float* __restrict__ w1b) {
    int d = blockIdx.x, b = blockIdx.y;
    int wid = threadIdx.x >> 5, lid = threadIdx.x & 31;
    __shared__ float sm[DD];
    for (int k = threadIdx.x; k < DD; k += 128) sm[k] = meta[b * DD + k];
    __syncthreads();
#pragma unroll 4
    for (int j = 0; j < 32; j++) {
        int c = wid * 32 + j;
        const float4* row = (const float4*)(w1w + (size_t)(c * DD + d) * DD);
        float acc = 0.f;
#pragma unroll
        for (int q = 0; q < 2; q++) {
            int i4 = lid + 32 * q;
            float4 v = row[i4];
            acc += v.x * sm[i4 * 4] + v.y * sm[i4 * 4 + 1]
                 + v.z * sm[i4 * 4 + 2] + v.w * sm[i4 * 4 + 3];
        }
#pragma unroll
        for (int off = 16; off > 0; off >>= 1)
            acc += __shfl_down_sync(0xffffffffu, acc, off);
        if (lid == 0) g_wm1t[((size_t)b * DD + d) * INCC + c] = acc + w1b[c * DD + d];
    }
}

// ---------------------------------------------------------------
// 2) wm2: hypernet conv weights -> hi/lo bf16, GATE-INTERLEAVED row order.
//    orig out-channel o (gate G = o>>6, ch = o&63) -> row p = (ch>>3)*32 + G*8 + (ch&7)
__global__ void k_wm2(const float* __restrict__ w2w, const float* __restrict__ w2b) {
    int o = blockIdx.x, b = blockIdx.y, c = threadIdx.x;   // 128 threads
    __shared__ float sw[NN * DD];
    for (int i = threadIdx.x; i < NN * DD; i += INCC)
        sw[i] = w2w[(size_t)o * NN * DD + i];
    __syncthreads();
    float acc[NN];
#pragma unroll
    for (int n = 0; n < NN; n++) acc[n] = 0.f;
    const float* a = g_wm1t + (size_t)b * DD * INCC + c;
#pragma unroll 4
    for (int d = 0; d < DD; d++) {
        float av = a[(size_t)d * INCC];
#pragma unroll
        for (int n = 0; n < NN; n++) acc[n] += av * sw[n * DD + d];
    }
    int po = ((o & 63) >> 3) * 32 + (o >> 6) * 8 + (o & 7);
    __nv_bfloat16* rowb = g_wm2 + (size_t)(b * OUTC + po) * KROW;
#pragma unroll
    for (int n = 0; n < NN; n++)
        store_hilo(rowb, c * NN + n, acc[n] + w2b[o * NN + n]);
}

// ---------------------------------------------------------------
// 3) bm[b][o] = meta[b] . bl_w[o] + bl_b[o]  (original order)
__global__ void k_bm(const float* __restrict__ meta, const float* __restrict__ blw,
                     const float* __restrict__ blb) {
    int b = blockIdx.y;
    int wid = threadIdx.x >> 5, lid = threadIdx.x & 31;
    int o = blockIdx.x * 8 + wid;
    __shared__ float sm[DD];
    for (int k = threadIdx.x; k < DD; k += 256) sm[k] = meta[b * DD + k];
    __syncthreads();
    const float4* row = (const float4*)(blw + (size_t)o * DD);
    float acc = 0.f;
#pragma unroll
    for (int q = 0; q < 2; q++) {
        int i4 = lid + 32 * q;
        float4 v = row[i4];
        acc += v.x * sm[i4 * 4] + v.y * sm[i4 * 4 + 1]
             + v.z * sm[i4 * 4 + 2] + v.w * sm[i4 * 4 + 3];
    }
#pragma unroll
    for (int off = 16; off > 0; off >>= 1)
        acc += __shfl_down_sync(0xffffffffu, acc, off);
    if (lid == 0) g_bm[b * OUTC + o] = acc + blb[o];
}

// ---------------------------------------------------------------
// 4) offset = conv3x3(meta_info_offset) + bias -> (b, 18, 64, 64)
__global__ void k_off(const float* __restrict__ mo, const float* __restrict__ pw,
                      const float* __restrict__ pb) {
    int idx = blockIdx.x * 256 + threadIdx.x;
    if (idx >= BB * 18 * HW) return;
    int hw = idx % HW;
    int j = (idx / HW) % 18;
    int b = idx / (18 * HW);
    int y = hw / WW, x = hw % WW;
    const float* in = mo + (size_t)b * HW;
    float acc = pb[j];
#pragma unroll
    for (int u = 0; u < 3; u++) {
        int yy = y + u - 1;
        if (yy < 0 || yy >= HH) continue;
#pragma unroll
        for (int v = 0; v < 3; v++) {
            int xx = x + v - 1;
            if (xx < 0 || xx >= WW) continue;
            acc += pw[j * 9 + u * 3 + v] * in[yy * WW + xx];
        }
    }
    g_off[idx] = acc;
}

// ---------------------------------------------------------------
// 5) deformable bilinear sampling -> g_xoffT2[b][hw] rows (hi/lo bf16 packed)
__global__ void k_sample2() {
    int wid = threadIdx.x >> 5, lid = threadIdx.x & 31;
    int b = blockIdx.y;
    int hw = blockIdx.x * 8 + wid;
    int h = hw >> 6, w = hw & 63;
    __shared__ float s_w[8][NN][4];
    __shared__ int   s_i[8][NN][4];
    if (lid < NN) {
        int n = lid;
        float ox = g_off[((size_t)(b * 18) + n) * HW + hw];
        float oy = g_off[((size_t)(b * 18) + 9 + n) * HW + hw];
        float px = (float)(h + 1) + (float)(n / 3 - 1) + ox;
        float py = (float)(w + 1) + (float)(n % 3 - 1) + oy;
        float fx = floorf(px), fy = floorf(py);
        float ltx = fminf(fmaxf(fx,       0.f), 65.f);
        float lty = fminf(fmaxf(fy,       0.f), 65.f);
        float rbx = fminf(fmaxf(fx + 1.f, 0.f), 65.f);
        float rby = fminf(fmaxf(fy + 1.f, 0.f), 65.f);
        float pcx = fminf(fmaxf(px,       0.f), 65.f);
        float pcy = fminf(fmaxf(py,       0.f), 65.f);
        s_w[wid][n][0] = (1.f + ltx - pcx) * (1.f + lty - pcy);  // lt
        s_w[wid][n][1] = (1.f - rbx + pcx) * (1.f - rby + pcy);  // rb
        s_w[wid][n][2] = (1.f + ltx - pcx) * (1.f - rby + pcy);  // lb
        s_w[wid][n][3] = (1.f - rbx + pcx) * (1.f + lty - pcy);  // rt
        s_i[wid][n][0] = (int)ltx * HP + (int)lty;
        s_i[wid][n][1] = (int)rbx * HP + (int)rby;
        s_i[wid][n][2] = (int)ltx * HP + (int)rby;
        s_i[wid][n][3] = (int)rbx * HP + (int)lty;
    }
    __syncwarp();
    const float* xp = g_xpad + (size_t)b * INCC * HP * HP;
    __nv_bfloat16* orow = g_xoffT2 + ((size_t)(b * HW) + hw) * KROW;
#pragma unroll 4
    for (int i = 0; i < 36; i++) {
        int k = i * 32 + lid;
        int c = k / NN;
        int n = k - c * NN;
        const float* xc = xp + (size_t)c * (HP * HP);
        float v = s_w[wid][n][0] * xc[s_i[wid][n][0]]
                + s_w[wid][n][1] * xc[s_i[wid][n][1]]
                + s_w[wid][n][2] * xc[s_i[wid][n][2]]
                + s_w[wid][n][3] * xc[s_i[wid][n][3]];
        __nv_bfloat16 hi = __float2bfloat16(v);
        float lo = v - __bfloat162float(hi);
        orow[i * 64 + lid]      = hi;
        orow[i * 64 + 32 + lid] = __float2bfloat16(lo);
    }
}

// ---------------------------------------------------------------
// 6) bf16x3 mma GEMM + fused LSTM epilogue.
//    A rows gate-interleaved so each thread holds (i,f,o,g) of one channel.
#define GBM 128
#define GBN 128
#define GSTAGE_BYTES 32768           // A 16KB + B 16KB
#define GSMEM (2 * GSTAGE_BYTES)
#define GNK (KTOT / 32)              // 36

__global__ __launch_bounds__(256, 2) void k_gemm_fused(
        const float* __restrict__ ccur, float* __restrict__ out, int half) {
    extern __shared__ char smem[];
    int t = threadIdx.x, lane = t & 31, wid = t >> 5;
    int warp_m = wid & 3, warp_n = wid >> 2;
    int b = blockIdx.z;
    const __nv_bfloat16* Ab = g_wm2    + (size_t)(b * OUTC + blockIdx.y * GBM) * KROW;
    const __nv_bfloat16* Bb = g_xoffT2 + ((size_t)(b * HW) + blockIdx.x * GBN) * KROW;
    uint32_t sbase = smem_u32(smem);

    // per-lane ldmatrix geometry
    int arow_base = warp_m * 32 + (lane & 7) + ((lane >> 3) & 1) * 8;   // + tm*16
    uint32_t a_k = (uint32_t)(lane >> 4);                               // 0/1
    int brow_base = warp_n * 64 + (lane & 7) + ((lane >> 4) & 1) * 8;   // + tnp*16
    uint32_t b_k = (uint32_t)((lane >> 3) & 1);

    float acc[2][8][4];
#pragma unroll
    for (int i = 0; i < 2; i++)
#pragma unroll
        for (int j = 0; j < 8; j++)
#pragma unroll
            for (int q = 0; q < 4; q++) acc[i][j][q] = 0.f;

#define LOAD_STAGE(kt, s) do {                                                     \
    const __nv_bfloat16* A0 = Ab + (kt) * 64;                                      \
    const __nv_bfloat16* B0 = Bb + (kt) * 64;                                      \
    uint32_t sA = sbase + (s) * GSTAGE_BYTES;                                      \
    uint32_t sB = sA + 16384;                                                      \
    _Pragma("unroll")                                                              \
    for (int i = 0; i < 4; i++) {                                                  \
        int idx = i * 256 + t, row = idx >> 3, q = idx & 7;                        \
        CP_ASYNC16(sA + row * 128 + ((q ^ (row & 7)) << 4),                        \
                   A0 + (size_t)row * KROW + q * 8);                               \
    }                                                                              \
    _Pragma("unroll")                                                              \
    for (int i = 0; i < 4; i++) {                                                  \
        int idx = i * 256 + t, row = idx >> 3, q = idx & 7;                        \
        CP_ASYNC16(sB + row * 128 + ((q ^ (row & 7)) << 4),                        \
                   B0 + (size_t)row * KROW + q * 8);                               \
    }                                                                              \
} while (0)

    LOAD_STAGE(0, 0); CP_COMMIT();

    for (int kt = 0; kt < GNK; kt++) {
        if (kt + 1 < GNK) {
            LOAD_STAGE(kt + 1, (kt + 1) & 1);
            CP_COMMIT();
            asm volatile("cp.async.wait_group 1;" ::: "memory");
        } else {
            asm volatile("cp.async.wait_group 0;" ::: "memory");
        }
        __syncthreads();
        uint32_t sAst = sbase + (kt & 1) * GSTAGE_BYTES;
        uint32_t sBst = sAst + 16384;
#pragma unroll
        for (int ks = 0; ks < 2; ks++) {
            uint32_t chh = 2 * ks;         // hi chunk base; lo = +4
            uint32_t ah[2][4], al[2][4];
#pragma unroll
            for (int tm = 0; tm < 2; tm++) {
                int row = arow_base + tm * 16;
                uint32_t rb = sAst + row * 128;
                uint32_t rm = (uint32_t)(row & 7);
                LDMX4(ah[tm], rb + (((chh + a_k) ^ rm) << 4));
                LDMX4(al[tm], rb + (((chh + 4 + a_k) ^ rm) << 4));
            }
#pragma unroll
            for (int tnp = 0; tnp < 4; tnp++) {
                int row = brow_base + tnp * 16;
                uint32_t rb = sBst + row * 128;
                uint32_t rm = (uint32_t)(row & 7);
                uint32_t bh[4], bl[4];
                LDMX4(bh, rb + (((chh + b_k) ^ rm) << 4));
                LDMX4(bl, rb + (((chh + 4 + b_k) ^ rm) << 4));
#pragma unroll
                for (int tm = 0; tm < 2; tm++)
#pragma unroll
                    for (int j = 0; j < 2; j++) {
                        int tn = tnp * 2 + j;
                        mma_bf16(acc[tm][tn], ah[tm], bh + 2 * j);
                        mma_bf16(acc[tm][tn], ah[tm], bl + 2 * j);
                        mma_bf16(acc[tm][tn], al[tm], bh + 2 * j);
                    }
            }
        }
        __syncthreads();
    }

    // ---- fused LSTM epilogue ----
    // thread owns channel ch, gates: acc[0][tn][0,1]=i, [2,3]=f, acc[1][tn][0,1]=o, [2,3]=g
    int g = lane >> 2, c4 = lane & 3;
    int ch = (blockIdx.y * 4 + warp_m) * 8 + g;
    float bi = g_bm[b * OUTC +        ch];
    float bf = g_bm[b * OUTC +  64 + ch];
    float bo = g_bm[b * OUTC + 128 + ch];
    float bg = g_bm[b * OUTC + 192 + ch];
    const float* crow = ccur + ((size_t)(b * HID) + ch) * HW;
    float* hrow = out +        ((size_t)(b * HID) + ch) * HW;
    float* corow = out + half + ((size_t)(b * HID) + ch) * HW;
#pragma unroll
    for (int tn = 0; tn < 8; tn++) {
        int col = blockIdx.x * GBN + warp_n * 64 + tn * 8 + c4 * 2;
        float2 cp = *(const float2*)(crow + col);
        float2 hv, cv;
#pragma unroll
        for (int q = 0; q < 2; q++) {
            float iv = 1.f / (1.f + expf(-(acc[0][tn][q]     + bi)));
            float fv = 1.f / (1.f + expf(-(acc[0][tn][2 + q] + bf)));
            float ov = 1.f / (1.f + expf(-(acc[1][tn][q]     + bo)));
            float gv = tanhf(acc[1][tn][2 + q] + bg);
            float cpq = q ? cp.y : cp.x;
            float cn = fv * cpq + iv * gv;
            float hn = ov * tanhf(cn);
            if (q) { hv.y = hn; cv.y = cn; } else { hv.x = hn; cv.x = cn; }
        }
        *(float2*)(hrow + col) = hv;
        *(float2*)(corow + col) = cv;
    }
}

// ---------------------------------------------------------------
extern "C" void kernel_launch(void* const* d_in, const int* in_sizes, int n_in,
                              void* d_out, int out_size) {
    const float* input = (const float*)d_in[0];
    const float* hcur  = (const float*)d_in[1];
    const float* ccur  = (const float*)d_in[2];
    const float* meta  = (const float*)d_in[3];
    const float* mo    = (const float*)d_in[4];
    const float* w1w   = (const float*)d_in[5];
    const float* w1b   = (const float*)d_in[6];
    const float* w2w   = (const float*)d_in[7];
    const float* w2b   = (const float*)d_in[8];
    const float* blw   = (const float*)d_in[9];
    const float* blb   = (const float*)d_in[10];
    const float* pw    = (const float*)d_in[11];
    const float* pb    = (const float*)d_in[12];
    float* out = (float*)d_out;

    static int smem_set = 0;
    if (!smem_set) {
        cudaFuncSetAttribute(k_gemm_fused, cudaFuncAttributeMaxDynamicSharedMemorySize, GSMEM);
        smem_set = 1;
    }

    k_xpad<<<(BB * INCC * HP * HP + 255) / 256, 256>>>(input, hcur);
    k_wm1 <<<dim3(DD, BB), 128>>>(meta, w1w, w1b);
    k_wm2 <<<dim3(OUTC, BB), INCC>>>(w2w, w2b);
    k_bm  <<<dim3(OUTC / 8, BB), 256>>>(meta, blw, blb);
    k_off <<<(BB * 18 * HW + 255) / 256, 256>>>(mo, pw, pb);
    k_sample2<<<dim3(HW / 8, BB), 256>>>();
    k_gemm_fused<<<dim3(HW / GBN, OUTC / GBM, BB), 256, GSMEM>>>(ccur, out, out_size / 2);
}

// round 6
// speedup vs baseline: 1.4202x; 1.4202x over previous
#include <cuda_runtime.h>
#include <cuda_bf16.h>
#include <cstdint>
#include <math.h>

#define BB   4
#define CIN  64
#define HID  64
#define HH   64
#define WW   64
#define NN   9
#define DD   256
#define INCC 128
#define OUTC 256
#define HP   66
#define HW   4096
#define KTOT 1152         // INCC * NN
#define KROW (KTOT * 2)   // bf16 hi|lo packed row length (elements)

// ---- scratch (static device globals; no allocation allowed) ----
__device__ float g_xpad[BB * INCC * HP * HP];
__device__ float g_wm1t[BB * DD * INCC];
__device__ __nv_bfloat16 g_wm2[(size_t)BB * OUTC * KROW];    // A hi|lo, gate-interleaved rows
__device__ float g_bm[BB * OUTC];                             // original order
__device__ float g_off[BB * 18 * HW];
__device__ __nv_bfloat16 g_xoffT2[(size_t)BB * HW * KROW];   // B hi|lo packed

// ============================================================
__device__ __forceinline__ uint32_t smem_u32(const void* p) {
    uint32_t a;
    asm("{ .reg .u64 t; cvta.to.shared.u64 t, %1; cvt.u32.u64 %0, t; }" : "=r"(a) : "l"(p));
    return a;
}
#define CP_ASYNC16(dst, src) \
    asm volatile("cp.async.cg.shared.global [%0], [%1], 16;" :: "r"(dst), "l"(src))
#define CP_COMMIT() asm volatile("cp.async.commit_group;" ::: "memory")

#define LDMX4(r, addr) \
    asm volatile("ldmatrix.sync.aligned.m8n8.x4.shared.b16 {%0,%1,%2,%3}, [%4];" \
        : "=r"((r)[0]), "=r"((r)[1]), "=r"((r)[2]), "=r"((r)[3]) : "r"(addr))

__device__ __forceinline__ void mma_bf16(float* c, const uint32_t* a, const uint32_t* b) {
    asm volatile(
        "mma.sync.aligned.m16n8k16.row.col.f32.bf16.bf16.f32 "
        "{%0,%1,%2,%3}, {%4,%5,%6,%7}, {%8,%9}, {%0,%1,%2,%3};"
        : "+f"(c[0]), "+f"(c[1]), "+f"(c[2]), "+f"(c[3])
        : "r"(a[0]), "r"(a[1]), "r"(a[2]), "r"(a[3]), "r"(b[0]), "r"(b[1]));
}

__device__ __forceinline__ void store_hilo(__nv_bfloat16* rowbase, int k, float v) {
    __nv_bfloat16 hi = __float2bfloat16(v);
    float lo = v - __bfloat162float(hi);
    size_t base = (size_t)(k >> 5) * 64 + (k & 31);
    rowbase[base]      = hi;
    rowbase[base + 32] = __float2bfloat16(lo);
}

// ---------------------------------------------------------------
// 0) zero-padded concat(input, h_cur): (b, 128, 66, 66)
__global__ void k_xpad(const float* __restrict__ inp, const float* __restrict__ hcur) {
    int idx = blockIdx.x * 256 + threadIdx.x;
    if (idx >= BB * INCC * HP * HP) return;
    int xy = idx % (HP * HP);
    int bc = idx / (HP * HP);
    int y = xy / HP, x = xy % HP;
    int c = bc % INCC, b = bc / INCC;
    float v = 0.f;
    if (y >= 1 && y <= HH && x >= 1 && x <= WW) {
        int pix = (y - 1) * WW + (x - 1);
        if (c < CIN) v = inp[((size_t)(b * CIN + c)) * HW + pix];
        else         v = hcur[((size_t)(b * HID + (c - CIN))) * HW + pix];
    }
    g_xpad[idx] = v;
}

// ---------------------------------------------------------------
// 1) wm1t[b][d][c] = meta[b] . w1_w[c*D+d] + w1_b[c*D+d]   (warp-per-output)
__global__ void k_wm1(const float* __restrict__ meta, const float* __restrict__ w1w,
                      const float* __restrict__ w1b) {
    int d = blockIdx.x, b = blockIdx.y;
    int wid = threadIdx.x >> 5, lid = threadIdx.x & 31;
    __shared__ float sm[DD];
    for (int k = threadIdx.x; k < DD; k += 128) sm[k] = meta[b * DD + k];
    __syncthreads();
#pragma unroll 4
    for (int j = 0; j < 32; j++) {
        int c = wid * 32 + j;
        const float4* row = (const float4*)(w1w + (size_t)(c * DD + d) * DD);
        float acc = 0.f;
#pragma unroll
        for (int q = 0; q < 2; q++) {
            int i4 = lid + 32 * q;
            float4 v = row[i4];
            acc += v.x * sm[i4 * 4] + v.y * sm[i4 * 4 + 1]
                 + v.z * sm[i4 * 4 + 2] + v.w * sm[i4 * 4 + 3];
        }
#pragma unroll
        for (int off = 16; off > 0; off >>= 1)
            acc += __shfl_down_sync(0xffffffffu, acc, off);
        if (lid == 0) g_wm1t[((size_t)b * DD + d) * INCC + c] = acc + w1b[c * DD + d];
    }
}

// ---------------------------------------------------------------
// 2) wm2: hypernet conv weights -> hi/lo bf16, GATE-INTERLEAVED row order.
//    orig out-channel o (gate G = o>>6, ch = o&63) -> row p = (ch>>3)*32 + G*8 + (ch&7)
__global__ void k_wm2(const float* __restrict__ w2w, const float* __restrict__ w2b) {
    int o = blockIdx.x, b = blockIdx.y, c = threadIdx.x;   // 128 threads
    __shared__ float sw[NN * DD];
    for (int i = threadIdx.x; i < NN * DD; i += INCC)
        sw[i] = w2w[(size_t)o * NN * DD + i];
    __syncthreads();
    float acc[NN];
#pragma unroll
    for (int n = 0; n < NN; n++) acc[n] = 0.f;
    const float* a = g_wm1t + (size_t)b * DD * INCC + c;
#pragma unroll 4
    for (int d = 0; d < DD; d++) {
        float av = a[(size_t)d * INCC];
#pragma unroll
        for (int n = 0; n < NN; n++) acc[n] += av * sw[n * DD + d];
    }
    int po = ((o & 63) >> 3) * 32 + (o >> 6) * 8 + (o & 7);
    __nv_bfloat16* rowb = g_wm2 + (size_t)(b * OUTC + po) * KROW;
#pragma unroll
    for (int n = 0; n < NN; n++)
        store_hilo(rowb, c * NN + n, acc[n] + w2b[o * NN + n]);
}

// ---------------------------------------------------------------
// 3) bm[b][o] = meta[b] . bl_w[o] + bl_b[o]  (original order)
__global__ void k_bm(const float* __restrict__ meta, const float* __restrict__ blw,
                     const float* __restrict__ blb) {
    int b = blockIdx.y;
    int wid = threadIdx.x >> 5, lid = threadIdx.x & 31;
    int o = blockIdx.x * 8 + wid;
    __shared__ float sm[DD];
    for (int k = threadIdx.x; k < DD; k += 256) sm[k] = meta[b * DD + k];
    __syncthreads();
    const float4* row = (const float4*)(blw + (size_t)o * DD);
    float acc = 0.f;
#pragma unroll
    for (int q = 0; q < 2; q++) {
        int i4 = lid + 32 * q;
        float4 v = row[i4];
        acc += v.x * sm[i4 * 4] + v.y * sm[i4 * 4 + 1]
             + v.z * sm[i4 * 4 + 2] + v.w * sm[i4 * 4 + 3];
    }
#pragma unroll
    for (int off = 16; off > 0; off >>= 1)
        acc += __shfl_down_sync(0xffffffffu, acc, off);
    if (lid == 0) g_bm[b * OUTC + o] = acc + blb[o];
}

// ---------------------------------------------------------------
// 4) offset = conv3x3(meta_info_offset) + bias -> (b, 18, 64, 64)
__global__ void k_off(const float* __restrict__ mo, const float* __restrict__ pw,
                      const float* __restrict__ pb) {
    int idx = blockIdx.x * 256 + threadIdx.x;
    if (idx >= BB * 18 * HW) return;
    int hw = idx % HW;
    int j = (idx / HW) % 18;
    int b = idx / (18 * HW);
    int y = hw / WW, x = hw % WW;
    const float* in = mo + (size_t)b * HW;
    float acc = pb[j];
#pragma unroll
    for (int u = 0; u < 3; u++) {
        int yy = y + u - 1;
        if (yy < 0 || yy >= HH) continue;
#pragma unroll
        for (int v = 0; v < 3; v++) {
            int xx = x + v - 1;
            if (xx < 0 || xx >= WW) continue;
            acc += pw[j * 9 + u * 3 + v] * in[yy * WW + xx];
        }
    }
    g_off[idx] = acc;
}

// ---------------------------------------------------------------
// 5) deformable bilinear sampling -> g_xoffT2[b][hw] rows (hi/lo bf16 packed)
__global__ void k_sample2() {
    int wid = threadIdx.x >> 5, lid = threadIdx.x & 31;
    int b = blockIdx.y;
    int hw = blockIdx.x * 8 + wid;
    int h = hw >> 6, w = hw & 63;
    __shared__ float s_w[8][NN][4];
    __shared__ int   s_i[8][NN][4];
    if (lid < NN) {
        int n = lid;
        float ox = g_off[((size_t)(b * 18) + n) * HW + hw];
        float oy = g_off[((size_t)(b * 18) + 9 + n) * HW + hw];
        float px = (float)(h + 1) + (float)(n / 3 - 1) + ox;
        float py = (float)(w + 1) + (float)(n % 3 - 1) + oy;
        float fx = floorf(px), fy = floorf(py);
        float ltx = fminf(fmaxf(fx,       0.f), 65.f);
        float lty = fminf(fmaxf(fy,       0.f), 65.f);
        float rbx = fminf(fmaxf(fx + 1.f, 0.f), 65.f);
        float rby = fminf(fmaxf(fy + 1.f, 0.f), 65.f);
        float pcx = fminf(fmaxf(px,       0.f), 65.f);
        float pcy = fminf(fmaxf(py,       0.f), 65.f);
        s_w[wid][n][0] = (1.f + ltx - pcx) * (1.f + lty - pcy);  // lt
        s_w[wid][n][1] = (1.f - rbx + pcx) * (1.f - rby + pcy);  // rb
        s_w[wid][n][2] = (1.f + ltx - pcx) * (1.f - rby + pcy);  // lb
        s_w[wid][n][3] = (1.f - rbx + pcx) * (1.f + lty - pcy);  // rt
        s_i[wid][n][0] = (int)ltx * HP + (int)lty;
        s_i[wid][n][1] = (int)rbx * HP + (int)rby;
        s_i[wid][n][2] = (int)ltx * HP + (int)rby;
        s_i[wid][n][3] = (int)rbx * HP + (int)lty;
    }
    __syncwarp();
    const float* xp = g_xpad + (size_t)b * INCC * HP * HP;
    __nv_bfloat16* orow = g_xoffT2 + ((size_t)(b * HW) + hw) * KROW;
#pragma unroll 4
    for (int i = 0; i < 36; i++) {
        int k = i * 32 + lid;
        int c = k / NN;
        int n = k - c * NN;
        const float* xc = xp + (size_t)c * (HP * HP);
        float v = s_w[wid][n][0] * xc[s_i[wid][n][0]]
                + s_w[wid][n][1] * xc[s_i[wid][n][1]]
                + s_w[wid][n][2] * xc[s_i[wid][n][2]]
                + s_w[wid][n][3] * xc[s_i[wid][n][3]];
        __nv_bfloat16 hi = __float2bfloat16(v);
        float lo = v - __bfloat162float(hi);
        orow[i * 64 + lid]      = hi;
        orow[i * 64 + 32 + lid] = __float2bfloat16(lo);
    }
}

// ---------------------------------------------------------------
// 6) bf16x3 mma GEMM + fused LSTM epilogue. 3-stage pipeline (R4 scheduling),
//    ldmatrix fragment loads, no register cap (occupancy 1 by smem anyway).
#define GBM 128
#define GBN 128
#define GSTAGE_BYTES 32768           // A 16KB + B 16KB
#define GSMEM (3 * GSTAGE_BYTES)
#define GNK (KTOT / 32)              // 36

__global__ __launch_bounds__(256) void k_gemm_fused(
        const float* __restrict__ ccur, float* __restrict__ out, int half) {
    extern __shared__ char smem[];
    int t = threadIdx.x, lane = t & 31, wid = t >> 5;
    int warp_m = wid & 3, warp_n = wid >> 2;
    int b = blockIdx.z;
    const __nv_bfloat16* Ab = g_wm2    + (size_t)(b * OUTC + blockIdx.y * GBM) * KROW;
    const __nv_bfloat16* Bb = g_xoffT2 + ((size_t)(b * HW) + blockIdx.x * GBN) * KROW;
    uint32_t sbase = smem_u32(smem);

    // per-lane ldmatrix geometry (validated in R5: rel_err identical to scalar path)
    int arow_base = warp_m * 32 + (lane & 7) + ((lane >> 3) & 1) * 8;   // + tm*16
    uint32_t a_k = (uint32_t)(lane >> 4);                               // 0/1
    int brow_base = warp_n * 64 + (lane & 7) + ((lane >> 4) & 1) * 8;   // + tnp*16
    uint32_t b_k = (uint32_t)((lane >> 3) & 1);

    float acc[2][8][4];
#pragma unroll
    for (int i = 0; i < 2; i++)
#pragma unroll
        for (int j = 0; j < 8; j++)
#pragma unroll
            for (int q = 0; q < 4; q++) acc[i][j][q] = 0.f;

#define LOAD_STAGE(kt, s) do {                                                     \
    const __nv_bfloat16* A0 = Ab + (kt) * 64;                                      \
    const __nv_bfloat16* B0 = Bb + (kt) * 64;                                      \
    uint32_t sA = sbase + (s) * GSTAGE_BYTES;                                      \
    uint32_t sB = sA + 16384;                                                      \
    _Pragma("unroll")                                                              \
    for (int i = 0; i < 4; i++) {                                                  \
        int idx = i * 256 + t, row = idx >> 3, q = idx & 7;                        \
        CP_ASYNC16(sA + row * 128 + ((q ^ (row & 7)) << 4),                        \
                   A0 + (size_t)row * KROW + q * 8);                               \
    }                                                                              \
    _Pragma("unroll")                                                              \
    for (int i = 0; i < 4; i++) {                                                  \
        int idx = i * 256 + t, row = idx >> 3, q = idx & 7;                        \
        CP_ASYNC16(sB + row * 128 + ((q ^ (row & 7)) << 4),                        \
                   B0 + (size_t)row * KROW + q * 8);                               \
    }                                                                              \
} while (0)

    LOAD_STAGE(0, 0); CP_COMMIT();
    LOAD_STAGE(1, 1); CP_COMMIT();

    for (int kt = 0; kt < GNK; kt++) {
        asm volatile("cp.async.wait_group 1;" ::: "memory");
        __syncthreads();
        if (kt + 2 < GNK) { LOAD_STAGE(kt + 2, (kt + 2) % 3); }
        CP_COMMIT();
        uint32_t sAst = sbase + (kt % 3) * GSTAGE_BYTES;
        uint32_t sBst = sAst + 16384;
#pragma unroll
        for (int ks = 0; ks < 2; ks++) {
            uint32_t chh = 2 * ks;         // hi chunk base; lo = +4
            uint32_t ah[2][4], al[2][4];
#pragma unroll
            for (int tm = 0; tm < 2; tm++) {
                int row = arow_base + tm * 16;
                uint32_t rb = sAst + row * 128;
                uint32_t rm = (uint32_t)(row & 7);
                LDMX4(ah[tm], rb + (((chh + a_k) ^ rm) << 4));
                LDMX4(al[tm], rb + (((chh + 4 + a_k) ^ rm) << 4));
            }
#pragma unroll
            for (int tnp = 0; tnp < 4; tnp++) {
                int row = brow_base + tnp * 16;
                uint32_t rb = sBst + row * 128;
                uint32_t rm = (uint32_t)(row & 7);
                uint32_t bh[4], bl[4];
                LDMX4(bh, rb + (((chh + b_k) ^ rm) << 4));
                LDMX4(bl, rb + (((chh + 4 + b_k) ^ rm) << 4));
#pragma unroll
                for (int tm = 0; tm < 2; tm++)
#pragma unroll
                    for (int j = 0; j < 2; j++) {
                        int tn = tnp * 2 + j;
                        mma_bf16(acc[tm][tn], ah[tm], bh + 2 * j);
                        mma_bf16(acc[tm][tn], ah[tm], bl + 2 * j);
                        mma_bf16(acc[tm][tn], al[tm], bh + 2 * j);
                    }
            }
        }
        __syncthreads();
    }

    // ---- fused LSTM epilogue ----
    // thread owns channel ch; acc[0][tn][0,1]=i, [2,3]=f, acc[1][tn][0,1]=o, [2,3]=g
    int g = lane >> 2, c4 = lane & 3;
    int ch = (blockIdx.y * 4 + warp_m) * 8 + g;
    float bi = g_bm[b * OUTC +        ch];
    float bf = g_bm[b * OUTC +  64 + ch];
    float bo = g_bm[b * OUTC + 128 + ch];
    float bg = g_bm[b * OUTC + 192 + ch];
    const float* crow = ccur + ((size_t)(b * HID) + ch) * HW;
    float* hrow = out +        ((size_t)(b * HID) + ch) * HW;
    float* corow = out + half + ((size_t)(b * HID) + ch) * HW;
#pragma unroll
    for (int tn = 0; tn < 8; tn++) {
        int col = blockIdx.x * GBN + warp_n * 64 + tn * 8 + c4 * 2;
        float2 cp = *(const float2*)(crow + col);
        float2 hv, cv;
#pragma unroll
        for (int q = 0; q < 2; q++) {
            float iv = 1.f / (1.f + expf(-(acc[0][tn][q]     + bi)));
            float fv = 1.f / (1.f + expf(-(acc[0][tn][2 + q] + bf)));
            float ov = 1.f / (1.f + expf(-(acc[1][tn][q]     + bo)));
            float gv = tanhf(acc[1][tn][2 + q] + bg);
            float cpq = q ? cp.y : cp.x;
            float cn = fv * cpq + iv * gv;
            float hn = ov * tanhf(cn);
            if (q) { hv.y = hn; cv.y = cn; } else { hv.x = hn; cv.x = cn; }
        }
        *(float2*)(hrow + col) = hv;
        *(float2*)(corow + col) = cv;
    }
}

// ---------------------------------------------------------------
extern "C" void kernel_launch(void* const* d_in, const int* in_sizes, int n_in,
                              void* d_out, int out_size) {
    const float* input = (const float*)d_in[0];
    const float* hcur  = (const float*)d_in[1];
    const float* ccur  = (const float*)d_in[2];
    const float* meta  = (const float*)d_in[3];
    const float* mo    = (const float*)d_in[4];
    const float* w1w   = (const float*)d_in[5];
    const float* w1b   = (const float*)d_in[6];
    const float* w2w   = (const float*)d_in[7];
    const float* w2b   = (const float*)d_in[8];
    const float* blw   = (const float*)d_in[9];
    const float* blb   = (const float*)d_in[10];
    const float* pw    = (const float*)d_in[11];
    const float* pb    = (const float*)d_in[12];
    float* out = (float*)d_out;

    static int smem_set = 0;
    if (!smem_set) {
        cudaFuncSetAttribute(k_gemm_fused, cudaFuncAttributeMaxDynamicSharedMemorySize, GSMEM);
        smem_set = 1;
    }

    k_xpad<<<(BB * INCC * HP * HP + 255) / 256, 256>>>(input, hcur);
    k_wm1 <<<dim3(DD, BB), 128>>>(meta, w1w, w1b);
    k_wm2 <<<dim3(OUTC, BB), INCC>>>(w2w, w2b);
    k_bm  <<<dim3(OUTC / 8, BB), 256>>>(meta, blw, blb);
    k_off <<<(BB * 18 * HW + 255) / 256, 256>>>(mo, pw, pb);
    k_sample2<<<dim3(HW / 8, BB), 256>>>();
    k_gemm_fused<<<dim3(HW / GBN, OUTC / GBM, BB), 256, GSMEM>>>(ccur, out, out_size / 2);
}

// round 7
// speedup vs baseline: 1.4989x; 1.0554x over previous
#include <cuda_runtime.h>
#include <cuda_bf16.h>
#include <cstdint>
#include <math.h>

#define BB   4
#define CIN  64
#define HID  64
#define HH   64
#define WW   64
#define NN   9
#define DD   256
#define INCC 128
#define OUTC 256
#define HP   66
#define HW   4096
#define KTOT 1152         // INCC * NN
#define KROW (KTOT * 2)   // bf16 hi|lo packed row length (elements)

// ---- scratch (static device globals; no allocation allowed) ----
__device__ float g_xpad[BB * INCC * HP * HP];
__device__ float g_wm1t[BB * DD * INCC];
__device__ __nv_bfloat16 g_wm2[(size_t)BB * OUTC * KROW];    // A hi|lo, gate-interleaved rows
__device__ float g_bm[BB * OUTC];                             // original order
__device__ float g_off[BB * 18 * HW];
__device__ __nv_bfloat16 g_xoffT2[(size_t)BB * HW * KROW];   // B hi|lo packed

// ============================================================
__device__ __forceinline__ uint32_t smem_u32(const void* p) {
    uint32_t a;
    asm("{ .reg .u64 t; cvta.to.shared.u64 t, %1; cvt.u32.u64 %0, t; }" : "=r"(a) : "l"(p));
    return a;
}
#define CP_ASYNC16(dst, src) \
    asm volatile("cp.async.cg.shared.global [%0], [%1], 16;" :: "r"(dst), "l"(src))
#define CP_COMMIT() asm volatile("cp.async.commit_group;" ::: "memory")

#define LDMX4(r, addr) \
    asm volatile("ldmatrix.sync.aligned.m8n8.x4.shared.b16 {%0,%1,%2,%3}, [%4];" \
        : "=r"((r)[0]), "=r"((r)[1]), "=r"((r)[2]), "=r"((r)[3]) : "r"(addr))

__device__ __forceinline__ void mma_bf16(float* c, const uint32_t* a, const uint32_t* b) {
    asm volatile(
        "mma.sync.aligned.m16n8k16.row.col.f32.bf16.bf16.f32 "
        "{%0,%1,%2,%3}, {%4,%5,%6,%7}, {%8,%9}, {%0,%1,%2,%3};"
        : "+f"(c[0]), "+f"(c[1]), "+f"(c[2]), "+f"(c[3])
        : "r"(a[0]), "r"(a[1]), "r"(a[2]), "r"(a[3]), "r"(b[0]), "r"(b[1]));
}

__device__ __forceinline__ void store_hilo(__nv_bfloat16* rowbase, int k, float v) {
    __nv_bfloat16 hi = __float2bfloat16(v);
    float lo = v - __bfloat162float(hi);
    size_t base = (size_t)(k >> 5) * 64 + (k & 31);
    rowbase[base]      = hi;
    rowbase[base + 32] = __float2bfloat16(lo);
}

// ---------------------------------------------------------------
// 1) wm1t[b][d][c] = meta[b] . w1_w[c*D+d] + w1_b[c*D+d]   (warp-per-output)
__global__ void k_wm1(const float* __restrict__ meta, const float* __restrict__ w1w,
                      const float* __restrict__ w1b) {
    int d = blockIdx.x, b = blockIdx.y;
    int wid = threadIdx.x >> 5, lid = threadIdx.x & 31;
    __shared__ float sm[DD];
    for (int k = threadIdx.x; k < DD; k += 128) sm[k] = meta[b * DD + k];
    __syncthreads();
#pragma unroll 4
    for (int j = 0; j < 32; j++) {
        int c = wid * 32 + j;
        const float4* row = (const float4*)(w1w + (size_t)(c * DD + d) * DD);
        float acc = 0.f;
#pragma unroll
        for (int q = 0; q < 2; q++) {
            int i4 = lid + 32 * q;
            float4 v = row[i4];
            acc += v.x * sm[i4 * 4] + v.y * sm[i4 * 4 + 1]
                 + v.z * sm[i4 * 4 + 2] + v.w * sm[i4 * 4 + 3];
        }
#pragma unroll
        for (int off = 16; off > 0; off >>= 1)
            acc += __shfl_down_sync(0xffffffffu, acc, off);
        if (lid == 0) g_wm1t[((size_t)b * DD + d) * INCC + c] = acc + w1b[c * DD + d];
    }
}

// ---------------------------------------------------------------
// 2) wm2 + bm merged. blocks [0,256): wm2 for o=bx; blocks [256,288): bm.
__global__ void k_wm2bm(const float* __restrict__ w2w, const float* __restrict__ w2b,
                        const float* __restrict__ meta, const float* __restrict__ blw,
                        const float* __restrict__ blb) {
    int bx = blockIdx.x, b = blockIdx.y;
    if (bx < 256) {
        int o = bx, c = threadIdx.x;                        // 128 threads
        __shared__ float sw[NN * DD];
        for (int i = threadIdx.x; i < NN * DD; i += INCC)
            sw[i] = w2w[(size_t)o * NN * DD + i];
        __syncthreads();
        float acc[NN];
#pragma unroll
        for (int n = 0; n < NN; n++) acc[n] = 0.f;
        const float* a = g_wm1t + (size_t)b * DD * INCC + c;
#pragma unroll 4
        for (int d = 0; d < DD; d++) {
            float av = a[(size_t)d * INCC];
#pragma unroll
            for (int n = 0; n < NN; n++) acc[n] += av * sw[n * DD + d];
        }
        // gate-interleaved row order: o=(G,ch) -> (ch>>3)*32 + G*8 + (ch&7)
        int po = ((o & 63) >> 3) * 32 + (o >> 6) * 8 + (o & 7);
        __nv_bfloat16* rowb = g_wm2 + (size_t)(b * OUTC + po) * KROW;
#pragma unroll
        for (int n = 0; n < NN; n++)
            store_hilo(rowb, c * NN + n, acc[n] + w2b[o * NN + n]);
    } else {
        // bm: 32 blocks x 8 outputs (4 warps x 2)
        int wid = threadIdx.x >> 5, lid = threadIdx.x & 31;
        __shared__ float sm[DD];
        for (int k = threadIdx.x; k < DD; k += 128) sm[k] = meta[b * DD + k];
        __syncthreads();
#pragma unroll
        for (int j = 0; j < 2; j++) {
            int o = (bx - 256) * 8 + wid * 2 + j;
            const float4* row = (const float4*)(blw + (size_t)o * DD);
            float acc = 0.f;
#pragma unroll
            for (int q = 0; q < 2; q++) {
                int i4 = lid + 32 * q;
                float4 v = row[i4];
                acc += v.x * sm[i4 * 4] + v.y * sm[i4 * 4 + 1]
                     + v.z * sm[i4 * 4 + 2] + v.w * sm[i4 * 4 + 3];
            }
#pragma unroll
            for (int off = 16; off > 0; off >>= 1)
                acc += __shfl_down_sync(0xffffffffu, acc, off);
            if (lid == 0) g_bm[b * OUTC + o] = acc + blb[o];
        }
    }
}

// ---------------------------------------------------------------
// 3) prep = xpad + offset-conv merged (independent elementwise work)
#define NXPAD (BB * INCC * HP * HP)
#define NOFF  (BB * 18 * HW)
__global__ void k_prep(const float* __restrict__ inp, const float* __restrict__ hcur,
                       const float* __restrict__ mo, const float* __restrict__ pw,
                       const float* __restrict__ pb) {
    int idx = blockIdx.x * 256 + threadIdx.x;
    if (idx < NXPAD) {
        int xy = idx % (HP * HP);
        int bc = idx / (HP * HP);
        int y = xy / HP, x = xy % HP;
        int c = bc % INCC, b = bc / INCC;
        float v = 0.f;
        if (y >= 1 && y <= HH && x >= 1 && x <= WW) {
            int pix = (y - 1) * WW + (x - 1);
            if (c < CIN) v = inp[((size_t)(b * CIN + c)) * HW + pix];
            else         v = hcur[((size_t)(b * HID + (c - CIN))) * HW + pix];
        }
        g_xpad[idx] = v;
    } else {
        int id2 = idx - NXPAD;
        if (id2 >= NOFF) return;
        int hw = id2 % HW;
        int j = (id2 / HW) % 18;
        int b = id2 / (18 * HW);
        int y = hw / WW, x = hw % WW;
        const float* in = mo + (size_t)b * HW;
        float acc = pb[j];
#pragma unroll
        for (int u = 0; u < 3; u++) {
            int yy = y + u - 1;
            if (yy < 0 || yy >= HH) continue;
#pragma unroll
            for (int v2 = 0; v2 < 3; v2++) {
                int xx = x + v2 - 1;
                if (xx < 0 || xx >= WW) continue;
                acc += pw[j * 9 + u * 3 + v2] * in[yy * WW + xx];
            }
        }
        g_off[id2] = acc;
    }
}

// ---------------------------------------------------------------
// 4) deformable bilinear sampling -> g_xoffT2[b][hw] rows (hi/lo bf16 packed)
__global__ void k_sample2() {
    int wid = threadIdx.x >> 5, lid = threadIdx.x & 31;
    int b = blockIdx.y;
    int hw = blockIdx.x * 8 + wid;
    int h = hw >> 6, w = hw & 63;
    __shared__ float s_w[8][NN][4];
    __shared__ int   s_i[8][NN][4];
    if (lid < NN) {
        int n = lid;
        float ox = g_off[((size_t)(b * 18) + n) * HW + hw];
        float oy = g_off[((size_t)(b * 18) + 9 + n) * HW + hw];
        float px = (float)(h + 1) + (float)(n / 3 - 1) + ox;
        float py = (float)(w + 1) + (float)(n % 3 - 1) + oy;
        float fx = floorf(px), fy = floorf(py);
        float ltx = fminf(fmaxf(fx,       0.f), 65.f);
        float lty = fminf(fmaxf(fy,       0.f), 65.f);
        float rbx = fminf(fmaxf(fx + 1.f, 0.f), 65.f);
        float rby = fminf(fmaxf(fy + 1.f, 0.f), 65.f);
        float pcx = fminf(fmaxf(px,       0.f), 65.f);
        float pcy = fminf(fmaxf(py,       0.f), 65.f);
        s_w[wid][n][0] = (1.f + ltx - pcx) * (1.f + lty - pcy);  // lt
        s_w[wid][n][1] = (1.f - rbx + pcx) * (1.f - rby + pcy);  // rb
        s_w[wid][n][2] = (1.f + ltx - pcx) * (1.f - rby + pcy);  // lb
        s_w[wid][n][3] = (1.f - rbx + pcx) * (1.f + lty - pcy);  // rt
        s_i[wid][n][0] = (int)ltx * HP + (int)lty;
        s_i[wid][n][1] = (int)rbx * HP + (int)rby;
        s_i[wid][n][2] = (int)ltx * HP + (int)rby;
        s_i[wid][n][3] = (int)rbx * HP + (int)lty;
    }
    __syncwarp();
    const float* xp = g_xpad + (size_t)b * INCC * HP * HP;
    __nv_bfloat16* orow = g_xoffT2 + ((size_t)(b * HW) + hw) * KROW;
    // incremental (c, n): k = i*32 + lid; step: c += 3, n += 5 (mod 9)
    int c = lid / NN;          // lid < 32 -> c in 0..3
    int n = lid - c * NN;
#pragma unroll 6
    for (int i = 0; i < 36; i++) {
        const float* xc = xp + (size_t)c * (HP * HP);
        float v = s_w[wid][n][0] * xc[s_i[wid][n][0]]
                + s_w[wid][n][1] * xc[s_i[wid][n][1]]
                + s_w[wid][n][2] * xc[s_i[wid][n][2]]
                + s_w[wid][n][3] * xc[s_i[wid][n][3]];
        __nv_bfloat16 hi = __float2bfloat16(v);
        float lo = v - __bfloat162float(hi);
        orow[i * 64 + lid]      = hi;
        orow[i * 64 + 32 + lid] = __float2bfloat16(lo);
        c += 3; n += 5;
        if (n >= NN) { n -= NN; c += 1; }
    }
}

// ---------------------------------------------------------------
// 5) bf16x3 mma GEMM + fused LSTM epilogue. 3-stage pipeline, ldmatrix.
#define GBM 128
#define GBN 128
#define GSTAGE_BYTES 32768           // A 16KB + B 16KB
#define GSMEM (3 * GSTAGE_BYTES)
#define GNK (KTOT / 32)              // 36

__global__ __launch_bounds__(256) void k_gemm_fused(
        const float* __restrict__ ccur, float* __restrict__ out, int half) {
    extern __shared__ char smem[];
    int t = threadIdx.x, lane = t & 31, wid = t >> 5;
    int warp_m = wid & 3, warp_n = wid >> 2;
    int b = blockIdx.z;
    const __nv_bfloat16* Ab = g_wm2    + (size_t)(b * OUTC + blockIdx.y * GBM) * KROW;
    const __nv_bfloat16* Bb = g_xoffT2 + ((size_t)(b * HW) + blockIdx.x * GBN) * KROW;
    uint32_t sbase = smem_u32(smem);

    int arow_base = warp_m * 32 + (lane & 7) + ((lane >> 3) & 1) * 8;   // + tm*16
    uint32_t a_k = (uint32_t)(lane >> 4);                               // 0/1
    int brow_base = warp_n * 64 + (lane & 7) + ((lane >> 4) & 1) * 8;   // + tnp*16
    uint32_t b_k = (uint32_t)((lane >> 3) & 1);

    float acc[2][8][4];
#pragma unroll
    for (int i = 0; i < 2; i++)
#pragma unroll
        for (int j = 0; j < 8; j++)
#pragma unroll
            for (int q = 0; q < 4; q++) acc[i][j][q] = 0.f;

#define LOAD_STAGE(kt, s) do {                                                     \
    const __nv_bfloat16* A0 = Ab + (kt) * 64;                                      \
    const __nv_bfloat16* B0 = Bb + (kt) * 64;                                      \
    uint32_t sA = sbase + (s) * GSTAGE_BYTES;                                      \
    uint32_t sB = sA + 16384;                                                      \
    _Pragma("unroll")                                                              \
    for (int i = 0; i < 4; i++) {                                                  \
        int idx = i * 256 + t, row = idx >> 3, q = idx & 7;                        \
        CP_ASYNC16(sA + row * 128 + ((q ^ (row & 7)) << 4),                        \
                   A0 + (size_t)row * KROW + q * 8);                               \
    }                                                                              \
    _Pragma("unroll")                                                              \
    for (int i = 0; i < 4; i++) {                                                  \
        int idx = i * 256 + t, row = idx >> 3, q = idx & 7;                        \
        CP_ASYNC16(sB + row * 128 + ((q ^ (row & 7)) << 4),                        \
                   B0 + (size_t)row * KROW + q * 8);                               \
    }                                                                              \
} while (0)

    LOAD_STAGE(0, 0); CP_COMMIT();
    LOAD_STAGE(1, 1); CP_COMMIT();

    for (int kt = 0; kt < GNK; kt++) {
        asm volatile("cp.async.wait_group 1;" ::: "memory");
        __syncthreads();
        if (kt + 2 < GNK) { LOAD_STAGE(kt + 2, (kt + 2) % 3); }
        CP_COMMIT();
        uint32_t sAst = sbase + (kt % 3) * GSTAGE_BYTES;
        uint32_t sBst = sAst + 16384;
#pragma unroll
        for (int ks = 0; ks < 2; ks++) {
            uint32_t chh = 2 * ks;         // hi chunk base; lo = +4
            uint32_t ah[2][4], al[2][4];
#pragma unroll
            for (int tm = 0; tm < 2; tm++) {
                int row = arow_base + tm * 16;
                uint32_t rb = sAst + row * 128;
                uint32_t rm = (uint32_t)(row & 7);
                LDMX4(ah[tm], rb + (((chh + a_k) ^ rm) << 4));
                LDMX4(al[tm], rb + (((chh + 4 + a_k) ^ rm) << 4));
            }
#pragma unroll
            for (int tnp = 0; tnp < 4; tnp++) {
                int row = brow_base + tnp * 16;
                uint32_t rb = sBst + row * 128;
                uint32_t rm = (uint32_t)(row & 7);
                uint32_t bh[4], bl[4];
                LDMX4(bh, rb + (((chh + b_k) ^ rm) << 4));
                LDMX4(bl, rb + (((chh + 4 + b_k) ^ rm) << 4));
#pragma unroll
                for (int tm = 0; tm < 2; tm++)
#pragma unroll
                    for (int j = 0; j < 2; j++) {
                        int tn = tnp * 2 + j;
                        mma_bf16(acc[tm][tn], ah[tm], bh + 2 * j);
                        mma_bf16(acc[tm][tn], ah[tm], bl + 2 * j);
                        mma_bf16(acc[tm][tn], al[tm], bh + 2 * j);
                    }
            }
        }
        __syncthreads();
    }

    // ---- fused LSTM epilogue ----
    int g = lane >> 2, c4 = lane & 3;
    int ch = (blockIdx.y * 4 + warp_m) * 8 + g;
    float bi = g_bm[b * OUTC +        ch];
    float bf = g_bm[b * OUTC +  64 + ch];
    float bo = g_bm[b * OUTC + 128 + ch];
    float bg = g_bm[b * OUTC + 192 + ch];
    const float* crow = ccur + ((size_t)(b * HID) + ch) * HW;
    float* hrow = out +        ((size_t)(b * HID) + ch) * HW;
    float* corow = out + half + ((size_t)(b * HID) + ch) * HW;
#pragma unroll
    for (int tn = 0; tn < 8; tn++) {
        int col = blockIdx.x * GBN + warp_n * 64 + tn * 8 + c4 * 2;
        float2 cp = *(const float2*)(crow + col);
        float2 hv, cv;
#pragma unroll
        for (int q = 0; q < 2; q++) {
            float iv = 1.f / (1.f + expf(-(acc[0][tn][q]     + bi)));
            float fv = 1.f / (1.f + expf(-(acc[0][tn][2 + q] + bf)));
            float ov = 1.f / (1.f + expf(-(acc[1][tn][q]     + bo)));
            float gv = tanhf(acc[1][tn][2 + q] + bg);
            float cpq = q ? cp.y : cp.x;
            float cn = fv * cpq + iv * gv;
            float hn = ov * tanhf(cn);
            if (q) { hv.y = hn; cv.y = cn; } else { hv.x = hn; cv.x = cn; }
        }
        *(float2*)(hrow + col) = hv;
        *(float2*)(corow + col) = cv;
    }
}

// ---------------------------------------------------------------
extern "C" void kernel_launch(void* const* d_in, const int* in_sizes, int n_in,
                              void* d_out, int out_size) {
    const float* input = (const float*)d_in[0];
    const float* hcur  = (const float*)d_in[1];
    const float* ccur  = (const float*)d_in[2];
    const float* meta  = (const float*)d_in[3];
    const float* mo    = (const float*)d_in[4];
    const float* w1w   = (const float*)d_in[5];
    const float* w1b   = (const float*)d_in[6];
    const float* w2w   = (const float*)d_in[7];
    const float* w2b   = (const float*)d_in[8];
    const float* blw   = (const float*)d_in[9];
    const float* blb   = (const float*)d_in[10];
    const float* pw    = (const float*)d_in[11];
    const float* pb    = (const float*)d_in[12];
    float* out = (float*)d_out;

    static int smem_set = 0;
    if (!smem_set) {
        cudaFuncSetAttribute(k_gemm_fused, cudaFuncAttributeMaxDynamicSharedMemorySize, GSMEM);
        smem_set = 1;
    }

    // order chosen so ncu (-s 5 -c 1, observed = my launch #4) captures k_sample2
    k_wm1   <<<dim3(DD, BB), 128>>>(meta, w1w, w1b);
    k_wm2bm <<<dim3(288, BB), 128>>>(w2w, w2b, meta, blw, blb);
    k_prep  <<<(NXPAD + NOFF + 255) / 256, 256>>>(input, hcur, mo, pw, pb);
    k_sample2<<<dim3(HW / 8, BB), 256>>>();
    k_gemm_fused<<<dim3(HW / GBN, OUTC / GBM, BB), 256, GSMEM>>>(ccur, out, out_size / 2);
}

// round 8
// speedup vs baseline: 2.0890x; 1.3936x over previous
#include <cuda_runtime.h>
#include <cuda_bf16.h>
#include <cstdint>
#include <math.h>

#define BB   4
#define CIN  64
#define HID  64
#define HH   64
#define WW   64
#define NN   9
#define DD   256
#define INCC 128
#define OUTC 256
#define HP   66
#define HW   4096
#define KTOT 1152         // INCC * NN
#define KROW (KTOT * 2)   // bf16 hi|lo packed row length (elements)

// ---- scratch (static device globals; no allocation allowed) ----
__device__ float g_xpadT[BB * HP * HP * INCC];               // channel-last padded concat
__device__ float g_wm1t[BB * DD * INCC];
__device__ __nv_bfloat16 g_wm2[(size_t)BB * OUTC * KROW];    // A hi|lo, k'=n*128+c order
__device__ float g_bm[BB * OUTC];
__device__ float g_off[BB * 18 * HW];
__device__ __nv_bfloat16 g_xoffT2[(size_t)BB * HW * KROW];   // B hi|lo, k'=n*128+c order

// ============================================================
__device__ __forceinline__ uint32_t smem_u32(const void* p) {
    uint32_t a;
    asm("{ .reg .u64 t; cvta.to.shared.u64 t, %1; cvt.u32.u64 %0, t; }" : "=r"(a) : "l"(p));
    return a;
}
#define CP_ASYNC16(dst, src) \
    asm volatile("cp.async.cg.shared.global [%0], [%1], 16;" :: "r"(dst), "l"(src))
#define CP_COMMIT() asm volatile("cp.async.commit_group;" ::: "memory")

#define LDMX4(r, addr) \
    asm volatile("ldmatrix.sync.aligned.m8n8.x4.shared.b16 {%0,%1,%2,%3}, [%4];" \
        : "=r"((r)[0]), "=r"((r)[1]), "=r"((r)[2]), "=r"((r)[3]) : "r"(addr))

__device__ __forceinline__ void mma_bf16(float* c, const uint32_t* a, const uint32_t* b) {
    asm volatile(
        "mma.sync.aligned.m16n8k16.row.col.f32.bf16.bf16.f32 "
        "{%0,%1,%2,%3}, {%4,%5,%6,%7}, {%8,%9}, {%0,%1,%2,%3};"
        : "+f"(c[0]), "+f"(c[1]), "+f"(c[2]), "+f"(c[3])
        : "r"(a[0]), "r"(a[1]), "r"(a[2]), "r"(a[3]), "r"(b[0]), "r"(b[1]));
}

__device__ __forceinline__ void store_hilo(__nv_bfloat16* rowbase, int k, float v) {
    __nv_bfloat16 hi = __float2bfloat16(v);
    float lo = v - __bfloat162float(hi);
    size_t base = (size_t)(k >> 5) * 64 + (k & 31);
    rowbase[base]      = hi;
    rowbase[base + 32] = __float2bfloat16(lo);
}

__device__ __forceinline__ uint32_t pack_bf2(__nv_bfloat16 a, __nv_bfloat16 b) {
    __nv_bfloat162 t; t.x = a; t.y = b;
    return *reinterpret_cast<uint32_t*>(&t);
}

// ---------------------------------------------------------------
// 1) wm1t[b][d][c] = meta[b] . w1_w[c*D+d] + w1_b[c*D+d]   (warp-per-output)
__global__ void k_wm1(const float* __restrict__ meta, const float* __restrict__ w1w,
                      const float* __restrict__ w1b) {
    int d = blockIdx.x, b = blockIdx.y;
    int wid = threadIdx.x >> 5, lid = threadIdx.x & 31;
    __shared__ float sm[DD];
    for (int k = threadIdx.x; k < DD; k += 128) sm[k] = meta[b * DD + k];
    __syncthreads();
#pragma unroll 4
    for (int j = 0; j < 32; j++) {
        int c = wid * 32 + j;
        const float4* row = (const float4*)(w1w + (size_t)(c * DD + d) * DD);
        float acc = 0.f;
#pragma unroll
        for (int q = 0; q < 2; q++) {
            int i4 = lid + 32 * q;
            float4 v = row[i4];
            acc += v.x * sm[i4 * 4] + v.y * sm[i4 * 4 + 1]
                 + v.z * sm[i4 * 4 + 2] + v.w * sm[i4 * 4 + 3];
        }
#pragma unroll
        for (int off = 16; off > 0; off >>= 1)
            acc += __shfl_down_sync(0xffffffffu, acc, off);
        if (lid == 0) g_wm1t[((size_t)b * DD + d) * INCC + c] = acc + w1b[c * DD + d];
    }
}

// ---------------------------------------------------------------
// 2) wm2 + bm merged. blocks [0,256): wm2 for o=bx (k'=n*128+c order); [256,288): bm.
__global__ void k_wm2bm(const float* __restrict__ w2w, const float* __restrict__ w2b,
                        const float* __restrict__ meta, const float* __restrict__ blw,
                        const float* __restrict__ blb) {
    int bx = blockIdx.x, b = blockIdx.y;
    if (bx < 256) {
        int o = bx, c = threadIdx.x;                        // 128 threads
        __shared__ float sw[NN * DD];
        for (int i = threadIdx.x; i < NN * DD; i += INCC)
            sw[i] = w2w[(size_t)o * NN * DD + i];
        __syncthreads();
        float acc[NN];
#pragma unroll
        for (int n = 0; n < NN; n++) acc[n] = 0.f;
        const float* a = g_wm1t + (size_t)b * DD * INCC + c;
#pragma unroll 4
        for (int d = 0; d < DD; d++) {
            float av = a[(size_t)d * INCC];
#pragma unroll
            for (int n = 0; n < NN; n++) acc[n] += av * sw[n * DD + d];
        }
        // gate-interleaved row order: o=(G,ch) -> (ch>>3)*32 + G*8 + (ch&7)
        int po = ((o & 63) >> 3) * 32 + (o >> 6) * 8 + (o & 7);
        __nv_bfloat16* rowb = g_wm2 + (size_t)(b * OUTC + po) * KROW;
#pragma unroll
        for (int n = 0; n < NN; n++)
            store_hilo(rowb, n * INCC + c, acc[n] + w2b[o * NN + n]);
    } else {
        int wid = threadIdx.x >> 5, lid = threadIdx.x & 31;
        __shared__ float sm[DD];
        for (int k = threadIdx.x; k < DD; k += 128) sm[k] = meta[b * DD + k];
        __syncthreads();
#pragma unroll
        for (int j = 0; j < 2; j++) {
            int o = (bx - 256) * 8 + wid * 2 + j;
            const float4* row = (const float4*)(blw + (size_t)o * DD);
            float acc = 0.f;
#pragma unroll
            for (int q = 0; q < 2; q++) {
                int i4 = lid + 32 * q;
                float4 v = row[i4];
                acc += v.x * sm[i4 * 4] + v.y * sm[i4 * 4 + 1]
                     + v.z * sm[i4 * 4 + 2] + v.w * sm[i4 * 4 + 3];
            }
#pragma unroll
            for (int off = 16; off > 0; off >>= 1)
                acc += __shfl_down_sync(0xffffffffu, acc, off);
            if (lid == 0) g_bm[b * OUTC + o] = acc + blb[o];
        }
    }
}

// ---------------------------------------------------------------
// 3) prep: channel-last padded concat (b,pix,c) + offset conv
#define NXPAD (BB * HP * HP * INCC)
#define NOFF  (BB * 18 * HW)
__global__ void k_prep(const float* __restrict__ inp, const float* __restrict__ hcur,
                       const float* __restrict__ mo, const float* __restrict__ pw,
                       const float* __restrict__ pb) {
    int idx = blockIdx.x * 256 + threadIdx.x;
    if (idx < NXPAD) {
        int c = idx & (INCC - 1);
        int rest = idx >> 7;
        int pix = rest % (HP * HP);
        int b = rest / (HP * HP);
        int y = pix / HP, x = pix % HP;
        float v = 0.f;
        if (y >= 1 && y <= HH && x >= 1 && x <= WW) {
            int p2 = (y - 1) * WW + (x - 1);
            if (c < CIN) v = inp[((size_t)(b * CIN + c)) * HW + p2];
            else         v = hcur[((size_t)(b * HID + (c - CIN))) * HW + p2];
        }
        g_xpadT[idx] = v;
    } else {
        int id2 = idx - NXPAD;
        if (id2 >= NOFF) return;
        int hw = id2 % HW;
        int j = (id2 / HW) % 18;
        int b = id2 / (18 * HW);
        int y = hw / WW, x = hw % WW;
        const float* in = mo + (size_t)b * HW;
        float acc = pb[j];
#pragma unroll
        for (int u = 0; u < 3; u++) {
            int yy = y + u - 1;
            if (yy < 0 || yy >= HH) continue;
#pragma unroll
            for (int v2 = 0; v2 < 3; v2++) {
                int xx = x + v2 - 1;
                if (xx < 0 || xx >= WW) continue;
                acc += pw[j * 9 + u * 3 + v2] * in[yy * WW + xx];
            }
        }
        g_off[id2] = acc;
    }
}

// ---------------------------------------------------------------
// 4) deformable bilinear sampling, channel-last gathers, k'=n*128+c output.
//    warp per pixel; per tap: 4 coalesced 512B corner reads, 2x 8B packed stores/lane.
__global__ void k_sample3() {
    int wid = threadIdx.x >> 5, lid = threadIdx.x & 31;
    int b = blockIdx.y;
    int hw = blockIdx.x * 8 + wid;
    int h = hw >> 6, w = hw & 63;
    __shared__ float s_w[8][NN][4];
    __shared__ int   s_i[8][NN][4];
    if (lid < NN) {
        int n = lid;
        float ox = g_off[((size_t)(b * 18) + n) * HW + hw];
        float oy = g_off[((size_t)(b * 18) + 9 + n) * HW + hw];
        float px = (float)(h + 1) + (float)(n / 3 - 1) + ox;
        float py = (float)(w + 1) + (float)(n % 3 - 1) + oy;
        float fx = floorf(px), fy = floorf(py);
        float ltx = fminf(fmaxf(fx,       0.f), 65.f);
        float lty = fminf(fmaxf(fy,       0.f), 65.f);
        float rbx = fminf(fmaxf(fx + 1.f, 0.f), 65.f);
        float rby = fminf(fmaxf(fy + 1.f, 0.f), 65.f);
        float pcx = fminf(fmaxf(px,       0.f), 65.f);
        float pcy = fminf(fmaxf(py,       0.f), 65.f);
        s_w[wid][n][0] = (1.f + ltx - pcx) * (1.f + lty - pcy);  // lt
        s_w[wid][n][1] = (1.f - rbx + pcx) * (1.f - rby + pcy);  // rb
        s_w[wid][n][2] = (1.f + ltx - pcx) * (1.f - rby + pcy);  // lb
        s_w[wid][n][3] = (1.f - rbx + pcx) * (1.f + lty - pcy);  // rt
        s_i[wid][n][0] = (int)ltx * HP + (int)lty;
        s_i[wid][n][1] = (int)rbx * HP + (int)rby;
        s_i[wid][n][2] = (int)ltx * HP + (int)rby;
        s_i[wid][n][3] = (int)rbx * HP + (int)lty;
    }
    __syncwarp();
    const float* xp = g_xpadT + (size_t)b * (HP * HP) * INCC;
    char* orow = (char*)(g_xoffT2 + ((size_t)(b * HW) + hw) * KROW);
    int lane8 = lid & 7, grp = lid >> 3;
#pragma unroll
    for (int n = 0; n < NN; n++) {
        float w0 = s_w[wid][n][0], w1 = s_w[wid][n][1];
        float w2 = s_w[wid][n][2], w3 = s_w[wid][n][3];
        const float4* p0 = (const float4*)(xp + (size_t)s_i[wid][n][0] * INCC);
        const float4* p1 = (const float4*)(xp + (size_t)s_i[wid][n][1] * INCC);
        const float4* p2 = (const float4*)(xp + (size_t)s_i[wid][n][2] * INCC);
        const float4* p3 = (const float4*)(xp + (size_t)s_i[wid][n][3] * INCC);
        float4 a0 = p0[lid], a1 = p1[lid], a2 = p2[lid], a3 = p3[lid];
        float v0 = w0 * a0.x + w1 * a1.x + w2 * a2.x + w3 * a3.x;
        float v1 = w0 * a0.y + w1 * a1.y + w2 * a2.y + w3 * a3.y;
        float v2 = w0 * a0.z + w1 * a1.z + w2 * a2.z + w3 * a3.z;
        float v3 = w0 * a0.w + w1 * a1.w + w2 * a2.w + w3 * a3.w;
        __nv_bfloat16 h0 = __float2bfloat16(v0), h1 = __float2bfloat16(v1);
        __nv_bfloat16 h2 = __float2bfloat16(v2), h3 = __float2bfloat16(v3);
        uint2 hv, lv;
        hv.x = pack_bf2(h0, h1);
        hv.y = pack_bf2(h2, h3);
        lv.x = pack_bf2(__float2bfloat16(v0 - __bfloat162float(h0)),
                        __float2bfloat16(v1 - __bfloat162float(h1)));
        lv.y = pack_bf2(__float2bfloat16(v2 - __bfloat162float(h2)),
                        __float2bfloat16(v3 - __bfloat162float(h3)));
        int base = (n * 4 + grp) * 128 + lane8 * 8;      // bytes into row
        *(uint2*)(orow + base)      = hv;                // 4 hi bf16
        *(uint2*)(orow + base + 64) = lv;                // 4 lo bf16
    }
}

// ---------------------------------------------------------------
// 5) bf16x3 mma GEMM + fused LSTM epilogue. 3-stage pipeline, ldmatrix.
#define GBM 128
#define GBN 128
#define GSTAGE_BYTES 32768           // A 16KB + B 16KB
#define GSMEM (3 * GSTAGE_BYTES)
#define GNK (KTOT / 32)              // 36

__global__ __launch_bounds__(256) void k_gemm_fused(
        const float* __restrict__ ccur, float* __restrict__ out, int half) {
    extern __shared__ char smem[];
    int t = threadIdx.x, lane = t & 31, wid = t >> 5;
    int warp_m = wid & 3, warp_n = wid >> 2;
    int b = blockIdx.z;
    const __nv_bfloat16* Ab = g_wm2    + (size_t)(b * OUTC + blockIdx.y * GBM) * KROW;
    const __nv_bfloat16* Bb = g_xoffT2 + ((size_t)(b * HW) + blockIdx.x * GBN) * KROW;
    uint32_t sbase = smem_u32(smem);

    int arow_base = warp_m * 32 + (lane & 7) + ((lane >> 3) & 1) * 8;   // + tm*16
    uint32_t a_k = (uint32_t)(lane >> 4);                               // 0/1
    int brow_base = warp_n * 64 + (lane & 7) + ((lane >> 4) & 1) * 8;   // + tnp*16
    uint32_t b_k = (uint32_t)((lane >> 3) & 1);

    float acc[2][8][4];
#pragma unroll
    for (int i = 0; i < 2; i++)
#pragma unroll
        for (int j = 0; j < 8; j++)
#pragma unroll
            for (int q = 0; q < 4; q++) acc[i][j][q] = 0.f;

#define LOAD_STAGE(kt, s) do {                                                     \
    const __nv_bfloat16* A0 = Ab + (kt) * 64;                                      \
    const __nv_bfloat16* B0 = Bb + (kt) * 64;                                      \
    uint32_t sA = sbase + (s) * GSTAGE_BYTES;                                      \
    uint32_t sB = sA + 16384;                                                      \
    _Pragma("unroll")                                                              \
    for (int i = 0; i < 4; i++) {                                                  \
        int idx = i * 256 + t, row = idx >> 3, q = idx & 7;                        \
        CP_ASYNC16(sA + row * 128 + ((q ^ (row & 7)) << 4),                        \
                   A0 + (size_t)row * KROW + q * 8);                               \
    }                                                                              \
    _Pragma("unroll")                                                              \
    for (int i = 0; i < 4; i++) {                                                  \
        int idx = i * 256 + t, row = idx >> 3, q = idx & 7;                        \
        CP_ASYNC16(sB + row * 128 + ((q ^ (row & 7)) << 4),                        \
                   B0 + (size_t)row * KROW + q * 8);                               \
    }                                                                              \
} while (0)

    LOAD_STAGE(0, 0); CP_COMMIT();
    LOAD_STAGE(1, 1); CP_COMMIT();

    for (int kt = 0; kt < GNK; kt++) {
        asm volatile("cp.async.wait_group 1;" ::: "memory");
        __syncthreads();
        if (kt + 2 < GNK) { LOAD_STAGE(kt + 2, (kt + 2) % 3); }
        CP_COMMIT();
        uint32_t sAst = sbase + (kt % 3) * GSTAGE_BYTES;
        uint32_t sBst = sAst + 16384;
#pragma unroll
        for (int ks = 0; ks < 2; ks++) {
            uint32_t chh = 2 * ks;         // hi chunk base; lo = +4
            uint32_t ah[2][4], al[2][4];
#pragma unroll
            for (int tm = 0; tm < 2; tm++) {
                int row = arow_base + tm * 16;
                uint32_t rb = sAst + row * 128;
                uint32_t rm = (uint32_t)(row & 7);
                LDMX4(ah[tm], rb + (((chh + a_k) ^ rm) << 4));
                LDMX4(al[tm], rb + (((chh + 4 + a_k) ^ rm) << 4));
            }
#pragma unroll
            for (int tnp = 0; tnp < 4; tnp++) {
                int row = brow_base + tnp * 16;
                uint32_t rb = sBst + row * 128;
                uint32_t rm = (uint32_t)(row & 7);
                uint32_t bh[4], bl[4];
                LDMX4(bh, rb + (((chh + b_k) ^ rm) << 4));
                LDMX4(bl, rb + (((chh + 4 + b_k) ^ rm) << 4));
#pragma unroll
                for (int tm = 0; tm < 2; tm++)
#pragma unroll
                    for (int j = 0; j < 2; j++) {
                        int tn = tnp * 2 + j;
                        mma_bf16(acc[tm][tn], ah[tm], bh + 2 * j);
                        mma_bf16(acc[tm][tn], ah[tm], bl + 2 * j);
                        mma_bf16(acc[tm][tn], al[tm], bh + 2 * j);
                    }
            }
        }
        __syncthreads();
    }

    // ---- fused LSTM epilogue ----
    int g = lane >> 2, c4 = lane & 3;
    int ch = (blockIdx.y * 4 + warp_m) * 8 + g;
    float bi = g_bm[b * OUTC +        ch];
    float bf = g_bm[b * OUTC +  64 + ch];
    float bo = g_bm[b * OUTC + 128 + ch];
    float bg = g_bm[b * OUTC + 192 + ch];
    const float* crow = ccur + ((size_t)(b * HID) + ch) * HW;
    float* hrow = out +        ((size_t)(b * HID) + ch) * HW;
    float* corow = out + half + ((size_t)(b * HID) + ch) * HW;
#pragma unroll
    for (int tn = 0; tn < 8; tn++) {
        int col = blockIdx.x * GBN + warp_n * 64 + tn * 8 + c4 * 2;
        float2 cp = *(const float2*)(crow + col);
        float2 hv, cv;
#pragma unroll
        for (int q = 0; q < 2; q++) {
            float iv = 1.f / (1.f + expf(-(acc[0][tn][q]     + bi)));
            float fv = 1.f / (1.f + expf(-(acc[0][tn][2 + q] + bf)));
            float ov = 1.f / (1.f + expf(-(acc[1][tn][q]     + bo)));
            float gv = tanhf(acc[1][tn][2 + q] + bg);
            float cpq = q ? cp.y : cp.x;
            float cn = fv * cpq + iv * gv;
            float hn = ov * tanhf(cn);
            if (q) { hv.y = hn; cv.y = cn; } else { hv.x = hn; cv.x = cn; }
        }
        *(float2*)(hrow + col) = hv;
        *(float2*)(corow + col) = cv;
    }
}

// ---------------------------------------------------------------
extern "C" void kernel_launch(void* const* d_in, const int* in_sizes, int n_in,
                              void* d_out, int out_size) {
    const float* input = (const float*)d_in[0];
    const float* hcur  = (const float*)d_in[1];
    const float* ccur  = (const float*)d_in[2];
    const float* meta  = (const float*)d_in[3];
    const float* mo    = (const float*)d_in[4];
    const float* w1w   = (const float*)d_in[5];
    const float* w1b   = (const float*)d_in[6];
    const float* w2w   = (const float*)d_in[7];
    const float* w2b   = (const float*)d_in[8];
    const float* blw   = (const float*)d_in[9];
    const float* blb   = (const float*)d_in[10];
    const float* pw    = (const float*)d_in[11];
    const float* pb    = (const float*)d_in[12];
    float* out = (float*)d_out;

    static int smem_set = 0;
    if (!smem_set) {
        cudaFuncSetAttribute(k_gemm_fused, cudaFuncAttributeMaxDynamicSharedMemorySize, GSMEM);
        smem_set = 1;
    }

    // launch order keeps the sampler in ncu's capture slot (#4)
    k_wm1   <<<dim3(DD, BB), 128>>>(meta, w1w, w1b);
    k_wm2bm <<<dim3(288, BB), 128>>>(w2w, w2b, meta, blw, blb);
    k_prep  <<<(NXPAD + NOFF + 255) / 256, 256>>>(input, hcur, mo, pw, pb);
    k_sample3<<<dim3(HW / 8, BB), 256>>>();
    k_gemm_fused<<<dim3(HW / GBN, OUTC / GBM, BB), 256, GSMEM>>>(ccur, out, out_size / 2);
}

// round 9
// speedup vs baseline: 2.1201x; 1.0149x over previous
#include <cuda_runtime.h>
#include <cuda_bf16.h>
#include <cstdint>
#include <math.h>

#define BB   4
#define CIN  64
#define HID  64
#define HH   64
#define WW   64
#define NN   9
#define DD   256
#define INCC 128
#define OUTC 256
#define HP   66
#define HW   4096
#define KTOT 1152         // INCC * NN
#define KROW (KTOT * 2)   // bf16 hi|lo packed row length (elements)

// ---- scratch (static device globals; no allocation allowed) ----
__device__ float g_xpadT[BB * HP * HP * INCC];               // channel-last padded concat
__device__ float g_wm1t[BB * DD * INCC];
__device__ __nv_bfloat16 g_wm2[(size_t)BB * OUTC * KROW];    // A hi|lo, k'=n*128+c order
__device__ float g_bm[BB * OUTC];
__device__ float g_off[BB * 18 * HW];
__device__ __nv_bfloat16 g_xoffT2[(size_t)BB * HW * KROW];   // B hi|lo, k'=n*128+c order

// ============================================================
__device__ __forceinline__ uint32_t smem_u32(const void* p) {
    uint32_t a;
    asm("{ .reg .u64 t; cvta.to.shared.u64 t, %1; cvt.u32.u64 %0, t; }" : "=r"(a) : "l"(p));
    return a;
}
#define CP_ASYNC16(dst, src) \
    asm volatile("cp.async.cg.shared.global [%0], [%1], 16;" :: "r"(dst), "l"(src))
#define CP_COMMIT() asm volatile("cp.async.commit_group;" ::: "memory")

#define LDMX4(r, addr) \
    asm volatile("ldmatrix.sync.aligned.m8n8.x4.shared.b16 {%0,%1,%2,%3}, [%4];" \
        : "=r"((r)[0]), "=r"((r)[1]), "=r"((r)[2]), "=r"((r)[3]) : "r"(addr))

__device__ __forceinline__ void mma_bf16(float* c, const uint32_t* a, const uint32_t* b) {
    asm volatile(
        "mma.sync.aligned.m16n8k16.row.col.f32.bf16.bf16.f32 "
        "{%0,%1,%2,%3}, {%4,%5,%6,%7}, {%8,%9}, {%0,%1,%2,%3};"
        : "+f"(c[0]), "+f"(c[1]), "+f"(c[2]), "+f"(c[3])
        : "r"(a[0]), "r"(a[1]), "r"(a[2]), "r"(a[3]), "r"(b[0]), "r"(b[1]));
}

__device__ __forceinline__ void store_hilo(__nv_bfloat16* rowbase, int k, float v) {
    __nv_bfloat16 hi = __float2bfloat16(v);
    float lo = v - __bfloat162float(hi);
    size_t base = (size_t)(k >> 5) * 64 + (k & 31);
    rowbase[base]      = hi;
    rowbase[base + 32] = __float2bfloat16(lo);
}

__device__ __forceinline__ uint32_t pack_bf2(__nv_bfloat16 a, __nv_bfloat16 b) {
    __nv_bfloat162 t; t.x = a; t.y = b;
    return *reinterpret_cast<uint32_t*>(&t);
}

// ---------------------------------------------------------------
// 1) prep (xpad transpose + offset conv) MERGED with wm1.
//    blocks [0, NPREP): elementwise prep; blocks [NPREP, NPREP+1024): wm1.
#define NXPAD (BB * HP * HP * INCC)
#define NOFF  (BB * 18 * HW)
#define NPREP ((NXPAD + NOFF) / 256)          // 9864, exact
__global__ void k_prep_wm1(const float* __restrict__ inp, const float* __restrict__ hcur,
                           const float* __restrict__ mo, const float* __restrict__ pw,
                           const float* __restrict__ pb,
                           const float* __restrict__ meta, const float* __restrict__ w1w,
                           const float* __restrict__ w1b) {
    int bx = blockIdx.x;
    if (bx < NPREP) {
        int idx = bx * 256 + threadIdx.x;
        if (idx < NXPAD) {
            int c = idx & (INCC - 1);
            int rest = idx >> 7;
            int pix = rest % (HP * HP);
            int b = rest / (HP * HP);
            int y = pix / HP, x = pix % HP;
            float v = 0.f;
            if (y >= 1 && y <= HH && x >= 1 && x <= WW) {
                int p2 = (y - 1) * WW + (x - 1);
                if (c < CIN) v = inp[((size_t)(b * CIN + c)) * HW + p2];
                else         v = hcur[((size_t)(b * HID + (c - CIN))) * HW + p2];
            }
            g_xpadT[idx] = v;
        } else {
            int id2 = idx - NXPAD;
            if (id2 >= NOFF) return;
            int hw = id2 % HW;
            int j = (id2 / HW) % 18;
            int b = id2 / (18 * HW);
            int y = hw / WW, x = hw % WW;
            const float* in = mo + (size_t)b * HW;
            float acc = pb[j];
#pragma unroll
            for (int u = 0; u < 3; u++) {
                int yy = y + u - 1;
                if (yy < 0 || yy >= HH) continue;
#pragma unroll
                for (int v2 = 0; v2 < 3; v2++) {
                    int xx = x + v2 - 1;
                    if (xx < 0 || xx >= WW) continue;
                    acc += pw[j * 9 + u * 3 + v2] * in[yy * WW + xx];
                }
            }
            g_off[id2] = acc;
        }
    } else {
        // wm1: block handles (d, b); 8 warps x 16 channels
        int i = bx - NPREP;
        int d = i & (DD - 1), b = i >> 8;
        int wid = threadIdx.x >> 5, lid = threadIdx.x & 31;
        __shared__ float sm[DD];
        if (threadIdx.x < DD) sm[threadIdx.x] = meta[b * DD + threadIdx.x];
        __syncthreads();
#pragma unroll 4
        for (int j = 0; j < 16; j++) {
            int c = wid * 16 + j;
            const float4* row = (const float4*)(w1w + (size_t)(c * DD + d) * DD);
            float acc = 0.f;
#pragma unroll
            for (int q = 0; q < 2; q++) {
                int i4 = lid + 32 * q;
                float4 v = row[i4];
                acc += v.x * sm[i4 * 4] + v.y * sm[i4 * 4 + 1]
                     + v.z * sm[i4 * 4 + 2] + v.w * sm[i4 * 4 + 3];
            }
#pragma unroll
            for (int off = 16; off > 0; off >>= 1)
                acc += __shfl_down_sync(0xffffffffu, acc, off);
            if (lid == 0) g_wm1t[((size_t)b * DD + d) * INCC + c] = acc + w1b[c * DD + d];
        }
    }
}

// ---------------------------------------------------------------
// 2) wm2 + bm merged. blocks [0,256): wm2 for o=bx (k'=n*128+c order); [256,288): bm.
__global__ void k_wm2bm(const float* __restrict__ w2w, const float* __restrict__ w2b,
                        const float* __restrict__ meta, const float* __restrict__ blw,
                        const float* __restrict__ blb) {
    int bx = blockIdx.x, b = blockIdx.y;
    if (bx < 256) {
        int o = bx, c = threadIdx.x;                        // 128 threads
        __shared__ float sw[NN * DD];
        for (int i = threadIdx.x; i < NN * DD; i += INCC)
            sw[i] = w2w[(size_t)o * NN * DD + i];
        __syncthreads();
        float acc[NN];
#pragma unroll
        for (int n = 0; n < NN; n++) acc[n] = 0.f;
        const float* a = g_wm1t + (size_t)b * DD * INCC + c;
#pragma unroll 4
        for (int d = 0; d < DD; d++) {
            float av = a[(size_t)d * INCC];
#pragma unroll
            for (int n = 0; n < NN; n++) acc[n] += av * sw[n * DD + d];
        }
        // gate-interleaved row order: o=(G,ch) -> (ch>>3)*32 + G*8 + (ch&7)
        int po = ((o & 63) >> 3) * 32 + (o >> 6) * 8 + (o & 7);
        __nv_bfloat16* rowb = g_wm2 + (size_t)(b * OUTC + po) * KROW;
#pragma unroll
        for (int n = 0; n < NN; n++)
            store_hilo(rowb, n * INCC + c, acc[n] + w2b[o * NN + n]);
    } else {
        int wid = threadIdx.x >> 5, lid = threadIdx.x & 31;
        __shared__ float sm[DD];
        for (int k = threadIdx.x; k < DD; k += 128) sm[k] = meta[b * DD + k];
        __syncthreads();
#pragma unroll
        for (int j = 0; j < 2; j++) {
            int o = (bx - 256) * 8 + wid * 2 + j;
            const float4* row = (const float4*)(blw + (size_t)o * DD);
            float acc = 0.f;
#pragma unroll
            for (int q = 0; q < 2; q++) {
                int i4 = lid + 32 * q;
                float4 v = row[i4];
                acc += v.x * sm[i4 * 4] + v.y * sm[i4 * 4 + 1]
                     + v.z * sm[i4 * 4 + 2] + v.w * sm[i4 * 4 + 3];
            }
#pragma unroll
            for (int off = 16; off > 0; off >>= 1)
                acc += __shfl_down_sync(0xffffffffu, acc, off);
            if (lid == 0) g_bm[b * OUTC + o] = acc + blb[o];
        }
    }
}

// ---------------------------------------------------------------
// 3) deformable bilinear sampling, channel-last gathers, k'=n*128+c output.
__global__ void k_sample3() {
    int wid = threadIdx.x >> 5, lid = threadIdx.x & 31;
    int b = blockIdx.y;
    int hw = blockIdx.x * 8 + wid;
    int h = hw >> 6, w = hw & 63;
    __shared__ float s_w[8][NN][4];
    __shared__ int   s_i[8][NN][4];
    if (lid < NN) {
        int n = lid;
        float ox = g_off[((size_t)(b * 18) + n) * HW + hw];
        float oy = g_off[((size_t)(b * 18) + 9 + n) * HW + hw];
        float px = (float)(h + 1) + (float)(n / 3 - 1) + ox;
        float py = (float)(w + 1) + (float)(n % 3 - 1) + oy;
        float fx = floorf(px), fy = floorf(py);
        float ltx = fminf(fmaxf(fx,       0.f), 65.f);
        float lty = fminf(fmaxf(fy,       0.f), 65.f);
        float rbx = fminf(fmaxf(fx + 1.f, 0.f), 65.f);
        float rby = fminf(fmaxf(fy + 1.f, 0.f), 65.f);
        float pcx = fminf(fmaxf(px,       0.f), 65.f);
        float pcy = fminf(fmaxf(py,       0.f), 65.f);
        s_w[wid][n][0] = (1.f + ltx - pcx) * (1.f + lty - pcy);  // lt
        s_w[wid][n][1] = (1.f - rbx + pcx) * (1.f - rby + pcy);  // rb
        s_w[wid][n][2] = (1.f + ltx - pcx) * (1.f - rby + pcy);  // lb
        s_w[wid][n][3] = (1.f - rbx + pcx) * (1.f + lty - pcy);  // rt
        s_i[wid][n][0] = (int)ltx * HP + (int)lty;
        s_i[wid][n][1] = (int)rbx * HP + (int)rby;
        s_i[wid][n][2] = (int)ltx * HP + (int)rby;
        s_i[wid][n][3] = (int)rbx * HP + (int)lty;
    }
    __syncwarp();
    const float* xp = g_xpadT + (size_t)b * (HP * HP) * INCC;
    char* orow = (char*)(g_xoffT2 + ((size_t)(b * HW) + hw) * KROW);
    int lane8 = lid & 7, grp = lid >> 3;
#pragma unroll
    for (int n = 0; n < NN; n++) {
        float w0 = s_w[wid][n][0], w1 = s_w[wid][n][1];
        float w2 = s_w[wid][n][2], w3 = s_w[wid][n][3];
        const float4* p0 = (const float4*)(xp + (size_t)s_i[wid][n][0] * INCC);
        const float4* p1 = (const float4*)(xp + (size_t)s_i[wid][n][1] * INCC);
        const float4* p2 = (const float4*)(xp + (size_t)s_i[wid][n][2] * INCC);
        const float4* p3 = (const float4*)(xp + (size_t)s_i[wid][n][3] * INCC);
        float4 a0 = p0[lid], a1 = p1[lid], a2 = p2[lid], a3 = p3[lid];
        float v0 = w0 * a0.x + w1 * a1.x + w2 * a2.x + w3 * a3.x;
        float v1 = w0 * a0.y + w1 * a1.y + w2 * a2.y + w3 * a3.y;
        float v2 = w0 * a0.z + w1 * a1.z + w2 * a2.z + w3 * a3.z;
        float v3 = w0 * a0.w + w1 * a1.w + w2 * a2.w + w3 * a3.w;
        __nv_bfloat16 h0 = __float2bfloat16(v0), h1 = __float2bfloat16(v1);
        __nv_bfloat16 h2 = __float2bfloat16(v2), h3 = __float2bfloat16(v3);
        uint2 hv, lv;
        hv.x = pack_bf2(h0, h1);
        hv.y = pack_bf2(h2, h3);
        lv.x = pack_bf2(__float2bfloat16(v0 - __bfloat162float(h0)),
                        __float2bfloat16(v1 - __bfloat162float(h1)));
        lv.y = pack_bf2(__float2bfloat16(v2 - __bfloat162float(h2)),
                        __float2bfloat16(v3 - __bfloat162float(h3)));
        int base = (n * 4 + grp) * 128 + lane8 * 8;      // bytes into row
        *(uint2*)(orow + base)      = hv;                // 4 hi bf16
        *(uint2*)(orow + base + 64) = lv;                // 4 lo bf16
    }
}

// ---------------------------------------------------------------
// 4) bf16x3 mma GEMM + fused LSTM epilogue. 3-stage pipeline, ldmatrix.
//    NOW IN NCU CAPTURE SLOT (launch #4).
#define GBM 128
#define GBN 128
#define GSTAGE_BYTES 32768           // A 16KB + B 16KB
#define GSMEM (3 * GSTAGE_BYTES)
#define GNK (KTOT / 32)              // 36

__global__ __launch_bounds__(256) void k_gemm_fused(
        const float* __restrict__ ccur, float* __restrict__ out, int half) {
    extern __shared__ char smem[];
    int t = threadIdx.x, lane = t & 31, wid = t >> 5;
    int warp_m = wid & 3, warp_n = wid >> 2;
    int b = blockIdx.z;
    const __nv_bfloat16* Ab = g_wm2    + (size_t)(b * OUTC + blockIdx.y * GBM) * KROW;
    const __nv_bfloat16* Bb = g_xoffT2 + ((size_t)(b * HW) + blockIdx.x * GBN) * KROW;
    uint32_t sbase = smem_u32(smem);

    int arow_base = warp_m * 32 + (lane & 7) + ((lane >> 3) & 1) * 8;   // + tm*16
    uint32_t a_k = (uint32_t)(lane >> 4);                               // 0/1
    int brow_base = warp_n * 64 + (lane & 7) + ((lane >> 4) & 1) * 8;   // + tnp*16
    uint32_t b_k = (uint32_t)((lane >> 3) & 1);

    float acc[2][8][4];
#pragma unroll
    for (int i = 0; i < 2; i++)
#pragma unroll
        for (int j = 0; j < 8; j++)
#pragma unroll
            for (int q = 0; q < 4; q++) acc[i][j][q] = 0.f;

#define LOAD_STAGE(kt, s) do {                                                     \
    const __nv_bfloat16* A0 = Ab + (kt) * 64;                                      \
    const __nv_bfloat16* B0 = Bb + (kt) * 64;                                      \
    uint32_t sA = sbase + (s) * GSTAGE_BYTES;                                      \
    uint32_t sB = sA + 16384;                                                      \
    _Pragma("unroll")                                                              \
    for (int i = 0; i < 4; i++) {                                                  \
        int idx = i * 256 + t, row = idx >> 3, q = idx & 7;                        \
        CP_ASYNC16(sA + row * 128 + ((q ^ (row & 7)) << 4),                        \
                   A0 + (size_t)row * KROW + q * 8);                               \
    }                                                                              \
    _Pragma("unroll")                                                              \
    for (int i = 0; i < 4; i++) {                                                  \
        int idx = i * 256 + t, row = idx >> 3, q = idx & 7;                        \
        CP_ASYNC16(sB + row * 128 + ((q ^ (row & 7)) << 4),                        \
                   B0 + (size_t)row * KROW + q * 8);                               \
    }                                                                              \
} while (0)

    LOAD_STAGE(0, 0); CP_COMMIT();
    LOAD_STAGE(1, 1); CP_COMMIT();

    for (int kt = 0; kt < GNK; kt++) {
        asm volatile("cp.async.wait_group 1;" ::: "memory");
        __syncthreads();
        if (kt + 2 < GNK) { LOAD_STAGE(kt + 2, (kt + 2) % 3); }
        CP_COMMIT();
        uint32_t sAst = sbase + (kt % 3) * GSTAGE_BYTES;
        uint32_t sBst = sAst + 16384;
#pragma unroll
        for (int ks = 0; ks < 2; ks++) {
            uint32_t chh = 2 * ks;         // hi chunk base; lo = +4
            uint32_t ah[2][4], al[2][4];
#pragma unroll
            for (int tm = 0; tm < 2; tm++) {
                int row = arow_base + tm * 16;
                uint32_t rb = sAst + row * 128;
                uint32_t rm = (uint32_t)(row & 7);
                LDMX4(ah[tm], rb + (((chh + a_k) ^ rm) << 4));
                LDMX4(al[tm], rb + (((chh + 4 + a_k) ^ rm) << 4));
            }
#pragma unroll
            for (int tnp = 0; tnp < 4; tnp++) {
                int row = brow_base + tnp * 16;
                uint32_t rb = sBst + row * 128;
                uint32_t rm = (uint32_t)(row & 7);
                uint32_t bh[4], bl[4];
                LDMX4(bh, rb + (((chh + b_k) ^ rm) << 4));
                LDMX4(bl, rb + (((chh + 4 + b_k) ^ rm) << 4));
#pragma unroll
                for (int tm = 0; tm < 2; tm++)
#pragma unroll
                    for (int j = 0; j < 2; j++) {
                        int tn = tnp * 2 + j;
                        mma_bf16(acc[tm][tn], ah[tm], bh + 2 * j);
                        mma_bf16(acc[tm][tn], ah[tm], bl + 2 * j);
                        mma_bf16(acc[tm][tn], al[tm], bh + 2 * j);
                    }
            }
        }
        __syncthreads();
    }

    // ---- fused LSTM epilogue ----
    int g = lane >> 2, c4 = lane & 3;
    int ch = (blockIdx.y * 4 + warp_m) * 8 + g;
    float bi = g_bm[b * OUTC +        ch];
    float bf = g_bm[b * OUTC +  64 + ch];
    float bo = g_bm[b * OUTC + 128 + ch];
    float bg = g_bm[b * OUTC + 192 + ch];
    const float* crow = ccur + ((size_t)(b * HID) + ch) * HW;
    float* hrow = out +        ((size_t)(b * HID) + ch) * HW;
    float* corow = out + half + ((size_t)(b * HID) + ch) * HW;
#pragma unroll
    for (int tn = 0; tn < 8; tn++) {
        int col = blockIdx.x * GBN + warp_n * 64 + tn * 8 + c4 * 2;
        float2 cp = *(const float2*)(crow + col);
        float2 hv, cv;
#pragma unroll
        for (int q = 0; q < 2; q++) {
            float iv = 1.f / (1.f + expf(-(acc[0][tn][q]     + bi)));
            float fv = 1.f / (1.f + expf(-(acc[0][tn][2 + q] + bf)));
            float ov = 1.f / (1.f + expf(-(acc[1][tn][q]     + bo)));
            float gv = tanhf(acc[1][tn][2 + q] + bg);
            float cpq = q ? cp.y : cp.x;
            float cn = fv * cpq + iv * gv;
            float hn = ov * tanhf(cn);
            if (q) { hv.y = hn; cv.y = cn; } else { hv.x = hn; cv.x = cn; }
        }
        *(float2*)(hrow + col) = hv;
        *(float2*)(corow + col) = cv;
    }
}

// ---------------------------------------------------------------
extern "C" void kernel_launch(void* const* d_in, const int* in_sizes, int n_in,
                              void* d_out, int out_size) {
    const float* input = (const float*)d_in[0];
    const float* hcur  = (const float*)d_in[1];
    const float* ccur  = (const float*)d_in[2];
    const float* meta  = (const float*)d_in[3];
    const float* mo    = (const float*)d_in[4];
    const float* w1w   = (const float*)d_in[5];
    const float* w1b   = (const float*)d_in[6];
    const float* w2w   = (const float*)d_in[7];
    const float* w2b   = (const float*)d_in[8];
    const float* blw   = (const float*)d_in[9];
    const float* blb   = (const float*)d_in[10];
    const float* pw    = (const float*)d_in[11];
    const float* pb    = (const float*)d_in[12];
    float* out = (float*)d_out;

    static int smem_set = 0;
    if (!smem_set) {
        cudaFuncSetAttribute(k_gemm_fused, cudaFuncAttributeMaxDynamicSharedMemorySize, GSMEM);
        smem_set = 1;
    }

    // 4 launches: ncu capture slot (#4) now lands on the GEMM
    k_prep_wm1<<<NPREP + DD * BB, 256>>>(input, hcur, mo, pw, pb, meta, w1w, w1b);
    k_wm2bm   <<<dim3(288, BB), 128>>>(w2w, w2b, meta, blw, blb);
    k_sample3 <<<dim3(HW / 8, BB), 256>>>();
    k_gemm_fused<<<dim3(HW / GBN, OUTC / GBM, BB), 256, GSMEM>>>(ccur, out, out_size / 2);
}